// round 1
// baseline (speedup 1.0000x reference)
#include <cuda_runtime.h>
#include <math.h>
#include <float.h>

// Problem constants (B,N,C,H,D) = (2, 2048, 1024, 16, 64)
#define B_    2
#define N_    2048
#define C_    1024
#define H_    16
#define D_    64
#define HD_   1024
#define QKVC_ 3072
#define M_    (B_*N_)          // 4096 rows
#define SCALE_ 0.125f          // D^-0.5

// Scratch: __device__ globals (no allocation allowed in kernel_launch).
// q/k/v stored [B,H,N,D]; att stored [B,N,H*D] so out-proj reads row-major.
__device__ float g_q[(size_t)B_*H_*N_*D_];
__device__ float g_k[(size_t)B_*H_*N_*D_];
__device__ float g_v[(size_t)B_*H_*N_*D_];
__device__ float g_att[(size_t)M_*HD_];

// ---------------------------------------------------------------------------
// Tiled fp32 GEMM: C[M x NC] = A[M x 1024] @ W[1024 x NC]
// BM=128, BN=128, BK=16, 256 threads, 8x8 register micro-tile.
// IS_QKV: scatter epilogue into g_q/g_k/g_v per the (h, d, qkv) reshape;
// otherwise plain row-major store to `out`.
// ---------------------------------------------------------------------------
template<int NC, bool IS_QKV>
__global__ void __launch_bounds__(256) gemm_kernel(const float* __restrict__ A_,
                                                   const float* __restrict__ W,
                                                   float* __restrict__ out) {
    __shared__ float As[16][132];   // A tile transposed: As[k][m]
    __shared__ float Bs[16][132];   // B tile: Bs[k][n]

    const float* A = IS_QKV ? A_ : (const float*)g_att;

    const int tid = threadIdx.x;
    const int tx  = tid & 15;       // 0..15 -> 8 output cols each
    const int ty  = tid >> 4;       // 0..15 -> 8 output rows each
    const int bm  = blockIdx.y * 128;
    const int bn  = blockIdx.x * 128;

    float acc[8][8];
#pragma unroll
    for (int i = 0; i < 8; i++)
#pragma unroll
        for (int j = 0; j < 8; j++) acc[i][j] = 0.f;

    for (int k0 = 0; k0 < 1024; k0 += 16) {
        // Load A tile 128x16 (2 float4 per thread), transpose into As[k][m]
#pragma unroll
        for (int i = 0; i < 2; i++) {
            int e4 = tid + i * 256;          // 0..511 float4s
            int m  = e4 >> 2;                // 0..127
            int kq = (e4 & 3) << 2;          // 0,4,8,12
            float4 v = *(const float4*)(A + (size_t)(bm + m) * 1024 + k0 + kq);
            As[kq + 0][m] = v.x;
            As[kq + 1][m] = v.y;
            As[kq + 2][m] = v.z;
            As[kq + 3][m] = v.w;
        }
        // Load B tile 16x128 (2 float4 per thread), coalesced rows
#pragma unroll
        for (int i = 0; i < 2; i++) {
            int e4 = tid + i * 256;
            int k  = e4 >> 5;                // 0..15
            int n4 = (e4 & 31) << 2;         // 0..124 step 4
            *(float4*)&Bs[k][n4] =
                *(const float4*)(W + (size_t)(k0 + k) * NC + bn + n4);
        }
        __syncthreads();

#pragma unroll
        for (int kk = 0; kk < 16; kk++) {
            float a[8], b[8];
            *(float4*)&a[0] = *(const float4*)&As[kk][ty * 8];
            *(float4*)&a[4] = *(const float4*)&As[kk][ty * 8 + 4];
            *(float4*)&b[0] = *(const float4*)&Bs[kk][tx * 8];
            *(float4*)&b[4] = *(const float4*)&Bs[kk][tx * 8 + 4];
#pragma unroll
            for (int i = 0; i < 8; i++)
#pragma unroll
                for (int j = 0; j < 8; j++)
                    acc[i][j] += a[i] * b[j];
        }
        __syncthreads();
    }

    if (IS_QKV) {
        // column c in [0,3072): reshape (H, D, 3): c = h*192 + d*3 + s
        // q gets pre-scaled by SCALE so attention logits are q.k + bias.
#pragma unroll
        for (int i = 0; i < 8; i++) {
            int r  = bm + ty * 8 + i;
            int bb = r >> 11;            // / 2048
            int n  = r & 2047;
#pragma unroll
            for (int j = 0; j < 8; j++) {
                int c  = bn + tx * 8 + j;
                int s  = c % 3;
                int hd = c / 3;
                int d  = hd & 63;
                int h  = hd >> 6;
                size_t idx = ((size_t)((bb * H_ + h) * N_ + n)) * D_ + d;
                float val = acc[i][j];
                if (s == 0)      g_q[idx] = val * SCALE_;
                else if (s == 1) g_k[idx] = val;
                else             g_v[idx] = val;
            }
        }
    } else {
#pragma unroll
        for (int i = 0; i < 8; i++) {
            int r = bm + ty * 8 + i;
            float4 v0 = make_float4(acc[i][0], acc[i][1], acc[i][2], acc[i][3]);
            float4 v1 = make_float4(acc[i][4], acc[i][5], acc[i][6], acc[i][7]);
            *(float4*)(out + (size_t)r * NC + bn + tx * 8)     = v0;
            *(float4*)(out + (size_t)r * NC + bn + tx * 8 + 4) = v1;
        }
    }
}

// ---------------------------------------------------------------------------
// Flash attention: per (b,h) pair, BR=128 query rows per block, stream over
// key tiles of BC=64. Online softmax. pos_bias streamed from global.
// Tiles in dynamic smem (96KB) with an XOR-4 swizzle so the row-strided
// LDS.128 reads in the S-GEMM are bank-conflict-free.
// ---------------------------------------------------------------------------
__device__ __forceinline__ int swz4(int r, int c4) { return c4 ^ ((r >> 2) & 7); }

__global__ void __launch_bounds__(256) attn_kernel(const float* __restrict__ pos_bias,
                                                   const unsigned char* __restrict__ mask) {
    extern __shared__ float sm[];
    float* Qs = sm;                  // 128 x 64
    float* Ks = Qs + 128 * 64;       // 64 x 64
    float* Vs = Ks + 64 * 64;        // 64 x 64
    float* Ps = Vs + 64 * 64;        // 128 x 64

    const int tid = threadIdx.x;
    const int tx  = tid & 15;        // 4 cols each
    const int ty  = tid >> 4;        // 8 rows each
    const int bh  = blockIdx.y;      // 0..31
    const int b   = bh >> 4;
    const int h   = bh & 15;
    const int q0  = blockIdx.x * 128;

    const float* qp = g_q + (size_t)bh * N_ * D_;
    const float* kp = g_k + (size_t)bh * N_ * D_;
    const float* vp = g_v + (size_t)bh * N_ * D_;

    // Load Q tile (already scaled by SCALE at QKV epilogue)
#pragma unroll
    for (int i = 0; i < 8; i++) {
        int e4 = tid + i * 256;
        int r  = e4 >> 4;            // 0..127
        int c4 = e4 & 15;
        *(float4*)&Qs[r * 64 + swz4(r, c4) * 4] =
            *(const float4*)(qp + (size_t)(q0 + r) * 64 + c4 * 4);
    }

    bool qm[8];
#pragma unroll
    for (int i = 0; i < 8; i++)
        qm[i] = mask[b * N_ + q0 + ty * 8 + i] != 0;

    float m_i[8], l_i[8], O[8][4];
#pragma unroll
    for (int i = 0; i < 8; i++) {
        m_i[i] = -INFINITY;
        l_i[i] = 0.f;
#pragma unroll
        for (int j = 0; j < 4; j++) O[i][j] = 0.f;
    }

    for (int kt = 0; kt < N_ / 64; kt++) {
        const int kk0 = kt * 64;
        __syncthreads();  // previous iteration's AV readers done with Ks/Vs

        // Load K and V tiles (64x64 each)
#pragma unroll
        for (int i = 0; i < 4; i++) {
            int e4 = tid + i * 256;
            int r  = e4 >> 4;
            int c4 = e4 & 15;
            *(float4*)&Ks[r * 64 + swz4(r, c4) * 4] =
                *(const float4*)(kp + (size_t)(kk0 + r) * 64 + c4 * 4);
            *(float4*)&Vs[r * 64 + swz4(r, c4) * 4] =
                *(const float4*)(vp + (size_t)(kk0 + r) * 64 + c4 * 4);
        }
        __syncthreads();

        // S = Q @ K^T  (8x4 per thread, vectorized over D)
        float s[8][4];
#pragma unroll
        for (int i = 0; i < 8; i++)
#pragma unroll
            for (int j = 0; j < 4; j++) s[i][j] = 0.f;

#pragma unroll 4
        for (int d4 = 0; d4 < 16; d4++) {
            float4 kb[4];
#pragma unroll
            for (int j = 0; j < 4; j++) {
                int kr = tx * 4 + j;
                kb[j] = *(const float4*)&Ks[kr * 64 + swz4(kr, d4) * 4];
            }
#pragma unroll
            for (int i = 0; i < 8; i++) {
                int qr = ty * 8 + i;
                float4 qa = *(const float4*)&Qs[qr * 64 + swz4(qr, d4) * 4];
#pragma unroll
                for (int j = 0; j < 4; j++) {
                    s[i][j] += qa.x * kb[j].x;
                    s[i][j] += qa.y * kb[j].y;
                    s[i][j] += qa.z * kb[j].z;
                    s[i][j] += qa.w * kb[j].w;
                }
            }
        }

        // Add relative-position bias + apply padding mask
        bool km[4];
#pragma unroll
        for (int j = 0; j < 4; j++)
            km[j] = mask[b * N_ + kk0 + tx * 4 + j] != 0;

#pragma unroll
        for (int i = 0; i < 8; i++) {
            int qr = q0 + ty * 8 + i;
            float4 bv = *(const float4*)(pos_bias +
                            ((size_t)h * N_ + qr) * N_ + kk0 + tx * 4);
            s[i][0] += bv.x; s[i][1] += bv.y; s[i][2] += bv.z; s[i][3] += bv.w;
#pragma unroll
            for (int j = 0; j < 4; j++)
                if (qm[i] || km[j]) s[i][j] = -FLT_MAX;
        }

        // Online softmax (row stats shared across the 16 tx lanes of a row group)
#pragma unroll
        for (int i = 0; i < 8; i++) {
            float rm = fmaxf(fmaxf(s[i][0], s[i][1]), fmaxf(s[i][2], s[i][3]));
#pragma unroll
            for (int off = 1; off < 16; off <<= 1)
                rm = fmaxf(rm, __shfl_xor_sync(0xffffffffu, rm, off));
            float nm    = fmaxf(m_i[i], rm);
            float alpha = __expf(m_i[i] - nm);
            float p0 = __expf(s[i][0] - nm);
            float p1 = __expf(s[i][1] - nm);
            float p2 = __expf(s[i][2] - nm);
            float p3 = __expf(s[i][3] - nm);
            int pr = ty * 8 + i;
            *(float4*)&Ps[pr * 64 + swz4(pr, tx) * 4] = make_float4(p0, p1, p2, p3);
            float rs = p0 + p1 + p2 + p3;
#pragma unroll
            for (int off = 1; off < 16; off <<= 1)
                rs += __shfl_xor_sync(0xffffffffu, rs, off);
            l_i[i] = l_i[i] * alpha + rs;
            m_i[i] = nm;
            O[i][0] *= alpha; O[i][1] *= alpha; O[i][2] *= alpha; O[i][3] *= alpha;
        }
        __syncthreads();

        // O += P @ V  (reduce over the 64 keys of this tile)
#pragma unroll 4
        for (int j4 = 0; j4 < 16; j4++) {
            float4 vb[4];
#pragma unroll
            for (int jj = 0; jj < 4; jj++) {
                int vr = j4 * 4 + jj;
                vb[jj] = *(const float4*)&Vs[vr * 64 + swz4(vr, tx) * 4];
            }
#pragma unroll
            for (int i = 0; i < 8; i++) {
                int pr = ty * 8 + i;
                float4 pa = *(const float4*)&Ps[pr * 64 + swz4(pr, j4) * 4];
                O[i][0] += pa.x * vb[0].x + pa.y * vb[1].x + pa.z * vb[2].x + pa.w * vb[3].x;
                O[i][1] += pa.x * vb[0].y + pa.y * vb[1].y + pa.z * vb[2].y + pa.w * vb[3].y;
                O[i][2] += pa.x * vb[0].z + pa.y * vb[1].z + pa.z * vb[2].z + pa.w * vb[3].z;
                O[i][3] += pa.x * vb[0].w + pa.y * vb[1].w + pa.z * vb[2].w + pa.w * vb[3].w;
            }
        }
    }

    // Normalize and write to g_att in [B, N, H*D] layout for the out-proj GEMM
#pragma unroll
    for (int i = 0; i < 8; i++) {
        float inv = 1.0f / l_i[i];
        int r = q0 + ty * 8 + i;
        float4 o = make_float4(O[i][0] * inv, O[i][1] * inv,
                               O[i][2] * inv, O[i][3] * inv);
        *(float4*)(g_att + ((size_t)(b * N_ + r)) * HD_ + h * 64 + tx * 4) = o;
    }
}

// ---------------------------------------------------------------------------
// Launch
// ---------------------------------------------------------------------------
extern "C" void kernel_launch(void* const* d_in, const int* in_sizes, int n_in,
                              void* d_out, int out_size) {
    const float*         x        = (const float*)d_in[0];
    const float*         pos_bias = (const float*)d_in[1];
    const float*         Wqkv     = (const float*)d_in[2];
    const float*         Wout     = (const float*)d_in[3];
    const unsigned char* mask     = (const unsigned char*)d_in[4];
    float*               out      = (float*)d_out;

    // 1) QKV projection with scatter epilogue (q pre-scaled by D^-0.5)
    gemm_kernel<QKVC_, true><<<dim3(QKVC_ / 128, M_ / 128), 256>>>(x, Wqkv, nullptr);

    // 2) Flash attention with pos-bias + padding mask
    const int smem_bytes = (128 + 64 + 64 + 128) * 64 * (int)sizeof(float);  // 96 KB
    cudaFuncSetAttribute(attn_kernel,
                         cudaFuncAttributeMaxDynamicSharedMemorySize, smem_bytes);
    attn_kernel<<<dim3(N_ / 128, B_ * H_), 256, smem_bytes>>>(pos_bias, mask);

    // 3) Output projection -> d_out
    gemm_kernel<HD_, false><<<dim3(HD_ / 128, M_ / 128), 256>>>(nullptr, Wout, out);
}

// round 3
// speedup vs baseline: 3.2428x; 3.2428x over previous
#include <cuda_runtime.h>
#include <math.h>
#include <float.h>
#include <stdint.h>

// Problem constants (B,N,C,H,D) = (2, 2048, 1024, 16, 64)
#define B_    2
#define N_    2048
#define C_    1024
#define H_    16
#define D_    64
#define HD_   1024
#define QKVC_ 3072
#define M_    (B_*N_)
#define SCALE_ 0.125f

// Scratch (allocation-free rule): q/k/v as [B,H,N,D], att as [B,N,H*D]
__device__ float g_q[(size_t)B_*H_*N_*D_];
__device__ float g_k[(size_t)B_*H_*N_*D_];
__device__ float g_v[(size_t)B_*H_*N_*D_];
__device__ float g_att[(size_t)M_*HD_];

// ---------------------------------------------------------------------------
// tf32 helpers
// ---------------------------------------------------------------------------
__device__ __forceinline__ uint32_t f2tf(float x) {
    uint32_t r;
    asm("cvt.rna.tf32.f32 %0, %1;" : "=r"(r) : "f"(x));
    return r;
}
__device__ __forceinline__ float f2tff(float x) { return __uint_as_float(f2tf(x)); }

// mma.sync m16n8k8 tf32: D = A*B + D (fp32 accum)
__device__ __forceinline__ void mma8(float c[4], const uint32_t a[4], const uint32_t b[2]) {
    asm volatile("mma.sync.aligned.m16n8k8.row.col.f32.tf32.tf32.f32 "
        "{%0,%1,%2,%3},{%4,%5,%6,%7},{%8,%9},{%0,%1,%2,%3};"
        : "+f"(c[0]), "+f"(c[1]), "+f"(c[2]), "+f"(c[3])
        : "r"(a[0]), "r"(a[1]), "r"(a[2]), "r"(a[3]), "r"(b[0]), "r"(b[1]));
}

// FMA-pipe exp: exp(x) = 2^(x*log2e); deg-5 Taylor for 2^f on [-0.5,0.5] (~3e-6 rel)
__device__ __forceinline__ float fast_exp(float x) {
    float y = x * 1.4426950408889634f;
    y = fmaxf(y, -126.0f);             // handles -FLT_MAX / -inf inputs -> ~0
    float r = rintf(y);
    float f = y - r;
    float p = 1.3333558146e-3f;
    p = fmaf(p, f, 9.6181291076e-3f);
    p = fmaf(p, f, 5.5504108665e-2f);
    p = fmaf(p, f, 2.4022650696e-1f);
    p = fmaf(p, f, 6.9314718056e-1f);
    p = fmaf(p, f, 1.0f);
    return p * __int_as_float(((int)r + 127) << 23);
}

// ---------------------------------------------------------------------------
// tf32 tensor-core GEMM: C[M x NC] = A[M x 1024] @ W[1024 x NC]
// 128x128 block tile, BK=32, 8 warps (4m x 2n), warp tile 32x64.
// ---------------------------------------------------------------------------
template<int NC, bool IS_QKV>
__global__ void __launch_bounds__(256) gemm_tc(const float* __restrict__ A_,
                                               const float* __restrict__ W,
                                               float* __restrict__ out) {
    __shared__ float As[128][36];    // [m][k], stride 36 -> conflict-free frag reads
    __shared__ float Bs[32][136];    // [k][n], stride 136

    const float* A = IS_QKV ? A_ : (const float*)g_att;

    const int tid  = threadIdx.x;
    const int lane = tid & 31, warp = tid >> 5;
    const int gid  = lane >> 2, tig = lane & 3;
    const int wm   = warp & 3, wn = warp >> 2;
    const int bm   = blockIdx.y * 128, bn = blockIdx.x * 128;

    float acc[2][8][4];
#pragma unroll
    for (int mi = 0; mi < 2; mi++)
#pragma unroll
        for (int ni = 0; ni < 8; ni++)
#pragma unroll
            for (int q = 0; q < 4; q++) acc[mi][ni][q] = 0.f;

    for (int k0 = 0; k0 < 1024; k0 += 32) {
        // A tile 128x32 (1024 float4s -> 4 iters of 256 threads)
#pragma unroll
        for (int i = 0; i < 4; i++) {
            int e  = tid + i * 256;
            int m  = (e & 7) | ((e >> 3) & 0x78);   // bits 0-2 and 6-9 of e
            int kq = ((e >> 3) & 7) << 2;           // bits 3-5 -> k offset
            float4 v = *(const float4*)(A + (size_t)(bm + m) * 1024 + k0 + kq);
            float4 t = make_float4(f2tff(v.x), f2tff(v.y), f2tff(v.z), f2tff(v.w));
            *(float4*)&As[m][kq] = t;
        }
        // B tile 32x128 (1024 float4s), coalesced rows
#pragma unroll
        for (int i = 0; i < 4; i++) {
            int e  = tid + i * 256;
            int k  = e >> 5;
            int n4 = (e & 31) << 2;
            float4 v = *(const float4*)(W + (size_t)(k0 + k) * NC + bn + n4);
            float4 t = make_float4(f2tff(v.x), f2tff(v.y), f2tff(v.z), f2tff(v.w));
            *(float4*)&Bs[k][n4] = t;
        }
        __syncthreads();

#pragma unroll
        for (int kk = 0; kk < 32; kk += 8) {
            uint32_t af[2][4];
#pragma unroll
            for (int mi = 0; mi < 2; mi++) {
                int r0 = wm * 32 + mi * 16 + gid;
                af[mi][0] = __float_as_uint(As[r0    ][kk + tig]);
                af[mi][1] = __float_as_uint(As[r0 + 8][kk + tig]);
                af[mi][2] = __float_as_uint(As[r0    ][kk + tig + 4]);
                af[mi][3] = __float_as_uint(As[r0 + 8][kk + tig + 4]);
            }
#pragma unroll
            for (int ni = 0; ni < 8; ni++) {
                uint32_t bf[2];
                int cc = wn * 64 + ni * 8 + gid;
                bf[0] = __float_as_uint(Bs[kk + tig    ][cc]);
                bf[1] = __float_as_uint(Bs[kk + tig + 4][cc]);
                mma8(acc[0][ni], af[0], bf);
                mma8(acc[1][ni], af[1], bf);
            }
        }
        __syncthreads();
    }

    if (IS_QKV) {
        // c = h*192 + d*3 + s ; q pre-scaled by D^-0.5
#pragma unroll
        for (int mi = 0; mi < 2; mi++)
#pragma unroll
            for (int ni = 0; ni < 8; ni++)
#pragma unroll
                for (int q = 0; q < 4; q++) {
                    int r = bm + wm * 32 + mi * 16 + gid + ((q >= 2) ? 8 : 0);
                    int c = bn + wn * 64 + ni * 8 + 2 * tig + (q & 1);
                    int bb = r >> 11, n = r & 2047;
                    int s  = c % 3,   hd = c / 3;
                    int d  = hd & 63, h = hd >> 6;
                    size_t idx = ((size_t)((bb * H_ + h) * N_ + n)) * D_ + d;
                    float val = acc[mi][ni][q];
                    if (s == 0)      g_q[idx] = val * SCALE_;
                    else if (s == 1) g_k[idx] = val;
                    else             g_v[idx] = val;
                }
    } else {
#pragma unroll
        for (int mi = 0; mi < 2; mi++)
#pragma unroll
            for (int ni = 0; ni < 8; ni++) {
                int r = bm + wm * 32 + mi * 16 + gid;
                int c = bn + wn * 64 + ni * 8 + 2 * tig;
                *(float2*)(out + (size_t)r * NC + c) =
                    make_float2(acc[mi][ni][0], acc[mi][ni][1]);
                *(float2*)(out + (size_t)(r + 8) * NC + c) =
                    make_float2(acc[mi][ni][2], acc[mi][ni][3]);
            }
    }
}

// ---------------------------------------------------------------------------
// Flash attention, tensor-core tf32. Each warp owns 16 q-rows; Q frags in
// registers; S in mma accumulators; softmax via fast_exp + shfl reductions;
// P through smem (own-warp rows -> __syncwarp only); PV via mma.
// ---------------------------------------------------------------------------
#define KS_STRIDE 68
#define VS_STRIDE 72
#define PS_STRIDE 68

__global__ void __launch_bounds__(256) attn_tc(const float* __restrict__ pos_bias,
                                               const unsigned char* __restrict__ mask) {
    extern __shared__ float smv[];
    float* Ks = smv;                           // [64][68]  K tile [key][d]
    float* Vs = Ks + 64 * KS_STRIDE;           // [64][72]  V tile [key][d]
    float* Ps = Vs + 64 * VS_STRIDE;           // [128][68] P tile [qrow][key]
    unsigned char* Ms = (unsigned char*)(Ps + 128 * PS_STRIDE);   // [64] key mask

    const int tid  = threadIdx.x;
    const int lane = tid & 31, wid = tid >> 5;
    const int gid  = lane >> 2, tig = lane & 3;
    const int b  = blockIdx.x;                 // fastest dim -> L2 bias sharing b=0/1
    const int q0 = blockIdx.y * 128;
    const int h  = blockIdx.z;
    const int bh = b * H_ + h;

    const float* qp = g_q + (size_t)bh * N_ * D_;
    const float* kp = g_k + (size_t)bh * N_ * D_;
    const float* vp = g_v + (size_t)bh * N_ * D_;

    const int qrow = q0 + wid * 16 + gid;      // rows qrow, qrow+8

    // Q fragments, register-resident for the whole kernel
    uint32_t qf[8][4];
#pragma unroll
    for (int kd = 0; kd < 8; kd++) {
        qf[kd][0] = f2tf(qp[(size_t)qrow       * D_ + kd * 8 + tig]);
        qf[kd][1] = f2tf(qp[(size_t)(qrow + 8) * D_ + kd * 8 + tig]);
        qf[kd][2] = f2tf(qp[(size_t)qrow       * D_ + kd * 8 + tig + 4]);
        qf[kd][3] = f2tf(qp[(size_t)(qrow + 8) * D_ + kd * 8 + tig + 4]);
    }
    const bool qm0 = mask[(size_t)b * N_ + qrow] != 0;
    const bool qm1 = mask[(size_t)b * N_ + qrow + 8] != 0;

    float m0 = -FLT_MAX, m1 = -FLT_MAX, l0 = 0.f, l1 = 0.f;
    float of[8][4];
#pragma unroll
    for (int df = 0; df < 8; df++)
#pragma unroll
        for (int q = 0; q < 4; q++) of[df][q] = 0.f;

    const float* bias0 = pos_bias + ((size_t)h * N_ + qrow) * N_;
    const float* bias1 = bias0 + 8 * (size_t)N_;

    float* prow0 = Ps + (wid * 16 + gid) * PS_STRIDE;
    float* prow1 = prow0 + 8 * PS_STRIDE;

    for (int kt = 0; kt < N_ / 64; kt++) {
        const int kk0 = kt * 64;
        __syncthreads();   // all warps done reading Ks/Vs from previous tile

        // Load K and V tiles: 64x64 each = 1024 float4s -> 4 iters of 256 threads
#pragma unroll
        for (int i = 0; i < 4; i++) {
            int e = tid + i * 256;
            int r = e >> 4, c4 = (e & 15) << 2;
            float4 kv = *(const float4*)(kp + (size_t)(kk0 + r) * D_ + c4);
            *(float4*)&Ks[r * KS_STRIDE + c4] =
                make_float4(f2tff(kv.x), f2tff(kv.y), f2tff(kv.z), f2tff(kv.w));
            float4 vv = *(const float4*)(vp + (size_t)(kk0 + r) * D_ + c4);
            *(float4*)&Vs[r * VS_STRIDE + c4] =
                make_float4(f2tff(vv.x), f2tff(vv.y), f2tff(vv.z), f2tff(vv.w));
        }
        if (tid < 16)
            ((uint32_t*)Ms)[tid] = *(const uint32_t*)(mask + (size_t)b * N_ + kk0 + tid * 4);
        __syncthreads();

        // S = Q @ K^T   (16 q-rows x 64 keys per warp)
        float sf[8][4];
#pragma unroll
        for (int ni = 0; ni < 8; ni++)
#pragma unroll
            for (int q = 0; q < 4; q++) sf[ni][q] = 0.f;

#pragma unroll
        for (int kd = 0; kd < 8; kd++) {
            uint32_t bfr[8][2];
#pragma unroll
            for (int ni = 0; ni < 8; ni++) {
                bfr[ni][0] = __float_as_uint(Ks[(ni * 8 + gid) * KS_STRIDE + kd * 8 + tig]);
                bfr[ni][1] = __float_as_uint(Ks[(ni * 8 + gid) * KS_STRIDE + kd * 8 + tig + 4]);
            }
#pragma unroll
            for (int ni = 0; ni < 8; ni++) mma8(sf[ni], qf[kd], bfr[ni]);
        }

        // Relative-position bias (fp32, batched loads for MLP) + padding mask
        float2 bv0[8], bv1[8];
#pragma unroll
        for (int ni = 0; ni < 8; ni++) {
            bv0[ni] = *(const float2*)(bias0 + kk0 + ni * 8 + 2 * tig);
            bv1[ni] = *(const float2*)(bias1 + kk0 + ni * 8 + 2 * tig);
        }
        float mloc0 = -FLT_MAX, mloc1 = -FLT_MAX;
#pragma unroll
        for (int ni = 0; ni < 8; ni++) {
            bool km0 = Ms[ni * 8 + 2 * tig] != 0;
            bool km1 = Ms[ni * 8 + 2 * tig + 1] != 0;
            sf[ni][0] = (qm0 | km0) ? -FLT_MAX : sf[ni][0] + bv0[ni].x;
            sf[ni][1] = (qm0 | km1) ? -FLT_MAX : sf[ni][1] + bv0[ni].y;
            sf[ni][2] = (qm1 | km0) ? -FLT_MAX : sf[ni][2] + bv1[ni].x;
            sf[ni][3] = (qm1 | km1) ? -FLT_MAX : sf[ni][3] + bv1[ni].y;
            mloc0 = fmaxf(mloc0, fmaxf(sf[ni][0], sf[ni][1]));
            mloc1 = fmaxf(mloc1, fmaxf(sf[ni][2], sf[ni][3]));
        }
        mloc0 = fmaxf(mloc0, __shfl_xor_sync(0xffffffffu, mloc0, 1));
        mloc0 = fmaxf(mloc0, __shfl_xor_sync(0xffffffffu, mloc0, 2));
        mloc1 = fmaxf(mloc1, __shfl_xor_sync(0xffffffffu, mloc1, 1));
        mloc1 = fmaxf(mloc1, __shfl_xor_sync(0xffffffffu, mloc1, 2));

        float nm0 = fmaxf(m0, mloc0), nm1 = fmaxf(m1, mloc1);
        float a0 = fast_exp(m0 - nm0), a1 = fast_exp(m1 - nm1);
        m0 = nm0; m1 = nm1;

        float rs0 = 0.f, rs1 = 0.f;
#pragma unroll
        for (int ni = 0; ni < 8; ni++) {
            float p0 = fast_exp(sf[ni][0] - nm0);
            float p1 = fast_exp(sf[ni][1] - nm0);
            float p2 = fast_exp(sf[ni][2] - nm1);
            float p3 = fast_exp(sf[ni][3] - nm1);
            rs0 += p0 + p1; rs1 += p2 + p3;
            *(float2*)(prow0 + ni * 8 + 2 * tig) = make_float2(f2tff(p0), f2tff(p1));
            *(float2*)(prow1 + ni * 8 + 2 * tig) = make_float2(f2tff(p2), f2tff(p3));
        }
        rs0 += __shfl_xor_sync(0xffffffffu, rs0, 1);
        rs0 += __shfl_xor_sync(0xffffffffu, rs0, 2);
        rs1 += __shfl_xor_sync(0xffffffffu, rs1, 1);
        rs1 += __shfl_xor_sync(0xffffffffu, rs1, 2);
        l0 = l0 * a0 + rs0;
        l1 = l1 * a1 + rs1;

#pragma unroll
        for (int df = 0; df < 8; df++) {
            of[df][0] *= a0; of[df][1] *= a0;
            of[df][2] *= a1; of[df][3] *= a1;
        }
        __syncwarp();   // P writes visible to own warp's reads

        // O += P @ V
#pragma unroll
        for (int kk = 0; kk < 8; kk++) {
            uint32_t af[4];
            af[0] = __float_as_uint(prow0[kk * 8 + tig]);
            af[1] = __float_as_uint(prow1[kk * 8 + tig]);
            af[2] = __float_as_uint(prow0[kk * 8 + tig + 4]);
            af[3] = __float_as_uint(prow1[kk * 8 + tig + 4]);
#pragma unroll
            for (int df = 0; df < 8; df++) {
                uint32_t bfr[2];
                bfr[0] = __float_as_uint(Vs[(kk * 8 + tig    ) * VS_STRIDE + df * 8 + gid]);
                bfr[1] = __float_as_uint(Vs[(kk * 8 + tig + 4) * VS_STRIDE + df * 8 + gid]);
                mma8(of[df], af, bfr);
            }
        }
    }

    // Normalize and write [B,N,H*D]
    float inv0 = 1.f / l0, inv1 = 1.f / l1;
    float* op0 = g_att + ((size_t)(b * N_ + qrow))     * HD_ + h * D_;
    float* op1 = g_att + ((size_t)(b * N_ + qrow + 8)) * HD_ + h * D_;
#pragma unroll
    for (int df = 0; df < 8; df++) {
        *(float2*)(op0 + df * 8 + 2 * tig) = make_float2(of[df][0] * inv0, of[df][1] * inv0);
        *(float2*)(op1 + df * 8 + 2 * tig) = make_float2(of[df][2] * inv1, of[df][3] * inv1);
    }
}

// ---------------------------------------------------------------------------
// Launch
// ---------------------------------------------------------------------------
extern "C" void kernel_launch(void* const* d_in, const int* in_sizes, int n_in,
                              void* d_out, int out_size) {
    const float*         x        = (const float*)d_in[0];
    const float*         pos_bias = (const float*)d_in[1];
    const float*         Wqkv     = (const float*)d_in[2];
    const float*         Wout     = (const float*)d_in[3];
    const unsigned char* mask     = (const unsigned char*)d_in[4];
    float*               out      = (float*)d_out;

    // 1) QKV projection (tf32 TC) with scatter epilogue
    gemm_tc<QKVC_, true><<<dim3(QKVC_ / 128, M_ / 128), 256>>>(x, Wqkv, nullptr);

    // 2) Flash attention (tf32 TC + poly softmax)
    const int smem_bytes = (64 * KS_STRIDE + 64 * VS_STRIDE + 128 * PS_STRIDE) * 4 + 64;
    cudaFuncSetAttribute(attn_tc,
                         cudaFuncAttributeMaxDynamicSharedMemorySize, smem_bytes);
    attn_tc<<<dim3(B_, N_ / 128, H_), 256, smem_bytes>>>(pos_bias, mask);

    // 3) Output projection (tf32 TC)
    gemm_tc<HD_, false><<<dim3(HD_ / 128, M_ / 128), 256>>>(nullptr, Wout, out);
}

// round 4
// speedup vs baseline: 3.8123x; 1.1756x over previous
#include <cuda_runtime.h>
#include <math.h>
#include <float.h>
#include <stdint.h>

// Problem constants (B,N,C,H,D) = (2, 2048, 1024, 16, 64)
#define B_    2
#define N_    2048
#define C_    1024
#define H_    16
#define D_    64
#define HD_   1024
#define QKVC_ 3072
#define M_    (B_*N_)
#define SCALE_ 0.125f

// Scratch (__device__ globals; no allocation allowed)
__device__ float g_q[(size_t)B_*H_*N_*D_];
__device__ float g_k[(size_t)B_*H_*N_*D_];
__device__ float g_v[(size_t)B_*H_*N_*D_];
__device__ float g_att[(size_t)M_*HD_];
__device__ float g_xt[(size_t)M_*C_];        // tf32-rounded x
__device__ float g_wqkvt[(size_t)C_*QKVC_];  // tf32-rounded Wqkv
__device__ float g_woutt[(size_t)HD_*C_];    // tf32-rounded Wout

// ---------------------------------------------------------------------------
// helpers
// ---------------------------------------------------------------------------
__device__ __forceinline__ uint32_t f2tf(float x) {
    uint32_t r;
    asm("cvt.rna.tf32.f32 %0, %1;" : "=r"(r) : "f"(x));
    return r;
}
__device__ __forceinline__ float f2tff(float x) { return __uint_as_float(f2tf(x)); }

__device__ __forceinline__ void mma8(float c[4], const uint32_t a[4], const uint32_t b[2]) {
    asm volatile("mma.sync.aligned.m16n8k8.row.col.f32.tf32.tf32.f32 "
        "{%0,%1,%2,%3},{%4,%5,%6,%7},{%8,%9},{%0,%1,%2,%3};"
        : "+f"(c[0]), "+f"(c[1]), "+f"(c[2]), "+f"(c[3])
        : "r"(a[0]), "r"(a[1]), "r"(a[2]), "r"(a[3]), "r"(b[0]), "r"(b[1]));
}

__device__ __forceinline__ uint32_t smem_u32(const void* p) {
    return (uint32_t)__cvta_generic_to_shared(p);
}
__device__ __forceinline__ void cp16(uint32_t dst, const void* src) {
    asm volatile("cp.async.cg.shared.global [%0], [%1], 16;" :: "r"(dst), "l"(src));
}
#define CP_COMMIT() asm volatile("cp.async.commit_group;" ::: "memory")
#define CP_WAIT0()  asm volatile("cp.async.wait_group 0;" ::: "memory")

// FMA-pipe exp (deg-5 poly 2^f, ~3e-6 rel)
__device__ __forceinline__ float fast_exp(float x) {
    float y = x * 1.4426950408889634f;
    y = fmaxf(y, -126.0f);
    float r = rintf(y);
    float f = y - r;
    float p = 1.3333558146e-3f;
    p = fmaf(p, f, 9.6181291076e-3f);
    p = fmaf(p, f, 5.5504108665e-2f);
    p = fmaf(p, f, 2.4022650696e-1f);
    p = fmaf(p, f, 6.9314718056e-1f);
    p = fmaf(p, f, 1.0f);
    return p * __int_as_float(((int)r + 127) << 23);
}

// ---------------------------------------------------------------------------
// Prep: round fp32 -> tf32(rna) stored as fp32 (grid-stride over float4)
// ---------------------------------------------------------------------------
__global__ void round_tf32(const float* __restrict__ in, float* __restrict__ out, int n4) {
    int i = blockIdx.x * blockDim.x + threadIdx.x;
    int stride = gridDim.x * blockDim.x;
    for (; i < n4; i += stride) {
        float4 v = ((const float4*)in)[i];
        ((float4*)out)[i] = make_float4(f2tff(v.x), f2tff(v.y), f2tff(v.z), f2tff(v.w));
    }
}

// ---------------------------------------------------------------------------
// tf32 TC GEMM, cp.async 2-stage pipeline. Inputs pre-rounded (no in-loop cvt).
// 128x128 tile, BK=32, 8 warps (4m x 2n).
// ---------------------------------------------------------------------------
#define AS_ELEMS 4608    // 128*36
#define BS_ELEMS 4352    // 32*136

template<int NC, bool IS_QKV>
__global__ void __launch_bounds__(256, 2) gemm_tc(const float* __restrict__ A_,
                                                  const float* __restrict__ W,
                                                  float* __restrict__ out) {
    extern __shared__ float sg[];
    float* As0 = sg;                  // 2 stages of [128][36]
    float* Bs0 = sg + 2 * AS_ELEMS;   // 2 stages of [32][136]

    const float* A = IS_QKV ? A_ : (const float*)g_att;

    const int tid  = threadIdx.x;
    const int lane = tid & 31, warp = tid >> 5;
    const int gid  = lane >> 2, tig = lane & 3;
    const int wm   = warp & 3, wn = warp >> 2;
    const int bm   = blockIdx.y * 128, bn = blockIdx.x * 128;

    auto load_tiles = [&](int s, int k0) {
        float* As = As0 + s * AS_ELEMS;
        float* Bs = Bs0 + s * BS_ELEMS;
#pragma unroll
        for (int i = 0; i < 4; i++) {
            int e  = tid + i * 256;
            int m  = (e & 7) | ((e >> 3) & 0x78);
            int kq = ((e >> 3) & 7) << 2;
            cp16(smem_u32(&As[m * 36 + kq]), A + (size_t)(bm + m) * 1024 + k0 + kq);
        }
#pragma unroll
        for (int i = 0; i < 4; i++) {
            int e  = tid + i * 256;
            int k  = e >> 5;
            int n4 = (e & 31) << 2;
            cp16(smem_u32(&Bs[k * 136 + n4]), W + (size_t)(k0 + k) * NC + bn + n4);
        }
    };

    float acc[2][8][4];
#pragma unroll
    for (int mi = 0; mi < 2; mi++)
#pragma unroll
        for (int ni = 0; ni < 8; ni++)
#pragma unroll
            for (int q = 0; q < 4; q++) acc[mi][ni][q] = 0.f;

    load_tiles(0, 0);
    CP_COMMIT();

    for (int it = 0; it < 32; it++) {
        CP_WAIT0();
        __syncthreads();
        if (it + 1 < 32) {
            load_tiles((it + 1) & 1, (it + 1) * 32);
            CP_COMMIT();
        }
        float* As = As0 + (it & 1) * AS_ELEMS;
        float* Bs = Bs0 + (it & 1) * BS_ELEMS;

#pragma unroll
        for (int kk = 0; kk < 32; kk += 8) {
            uint32_t af[2][4];
#pragma unroll
            for (int mi = 0; mi < 2; mi++) {
                int r0 = wm * 32 + mi * 16 + gid;
                af[mi][0] = __float_as_uint(As[(r0    ) * 36 + kk + tig]);
                af[mi][1] = __float_as_uint(As[(r0 + 8) * 36 + kk + tig]);
                af[mi][2] = __float_as_uint(As[(r0    ) * 36 + kk + tig + 4]);
                af[mi][3] = __float_as_uint(As[(r0 + 8) * 36 + kk + tig + 4]);
            }
#pragma unroll
            for (int ni = 0; ni < 8; ni++) {
                uint32_t bf[2];
                int cc = wn * 64 + ni * 8 + gid;
                bf[0] = __float_as_uint(Bs[(kk + tig    ) * 136 + cc]);
                bf[1] = __float_as_uint(Bs[(kk + tig + 4) * 136 + cc]);
                mma8(acc[0][ni], af[0], bf);
                mma8(acc[1][ni], af[1], bf);
            }
        }
        __syncthreads();
    }

    if (IS_QKV) {
        // c = h*192 + d*3 + s; q pre-scaled; all outputs tf32-rounded at store
#pragma unroll
        for (int mi = 0; mi < 2; mi++)
#pragma unroll
            for (int ni = 0; ni < 8; ni++)
#pragma unroll
                for (int q = 0; q < 4; q++) {
                    int r = bm + wm * 32 + mi * 16 + gid + ((q >= 2) ? 8 : 0);
                    int c = bn + wn * 64 + ni * 8 + 2 * tig + (q & 1);
                    int bb = r >> 11, n = r & 2047;
                    int s  = c % 3,   hd = c / 3;
                    int d  = hd & 63, h = hd >> 6;
                    size_t idx = ((size_t)((bb * H_ + h) * N_ + n)) * D_ + d;
                    float val = acc[mi][ni][q];
                    if (s == 0)      g_q[idx] = f2tff(val * SCALE_);
                    else if (s == 1) g_k[idx] = f2tff(val);
                    else             g_v[idx] = f2tff(val);
                }
    } else {
#pragma unroll
        for (int mi = 0; mi < 2; mi++)
#pragma unroll
            for (int ni = 0; ni < 8; ni++) {
                int r = bm + wm * 32 + mi * 16 + gid;
                int c = bn + wn * 64 + ni * 8 + 2 * tig;
                *(float2*)(out + (size_t)r * NC + c) =
                    make_float2(acc[mi][ni][0], acc[mi][ni][1]);
                *(float2*)(out + (size_t)(r + 8) * NC + c) =
                    make_float2(acc[mi][ni][2], acc[mi][ni][3]);
            }
    }
}

// ---------------------------------------------------------------------------
// Flash attention, tf32 TC, cp.async double-buffered K/V (pre-rounded).
// ---------------------------------------------------------------------------
#define KS_STRIDE 68
#define VS_STRIDE 72
#define PS_STRIDE 68
#define KS_ELEMS (64*KS_STRIDE)   // 4352
#define VS_ELEMS (64*VS_STRIDE)   // 4608
#define PS_ELEMS (128*PS_STRIDE)  // 8704
// smem: 2*KS + 2*VS + PS floats, then 2x64B mask
#define ATTN_SMEM_FLOATS (2*KS_ELEMS + 2*VS_ELEMS + PS_ELEMS)
#define ATTN_SMEM_BYTES  (ATTN_SMEM_FLOATS*4 + 128)

__global__ void __launch_bounds__(256, 2) attn_tc(const float* __restrict__ pos_bias,
                                                  const unsigned char* __restrict__ mask) {
    extern __shared__ float smv[];
    float* Ks0 = smv;                        // 2 x [64][68]
    float* Vs0 = smv + 2 * KS_ELEMS;         // 2 x [64][72]
    float* Ps  = smv + 2 * KS_ELEMS + 2 * VS_ELEMS;  // [128][68]
    unsigned char* Ms0 = (unsigned char*)(Ps + PS_ELEMS);  // 2 x [64]

    const int tid  = threadIdx.x;
    const int lane = tid & 31, wid = tid >> 5;
    const int gid  = lane >> 2, tig = lane & 3;
    const int b  = blockIdx.x;
    const int q0 = blockIdx.y * 128;
    const int h  = blockIdx.z;
    const int bh = b * H_ + h;

    const float* qp = g_q + (size_t)bh * N_ * D_;
    const float* kp = g_k + (size_t)bh * N_ * D_;
    const float* vp = g_v + (size_t)bh * N_ * D_;
    const unsigned char* maskp = mask + (size_t)b * N_;

    auto loadKV = [&](int s, int kk0) {
        float* Ksb = Ks0 + s * KS_ELEMS;
        float* Vsb = Vs0 + s * VS_ELEMS;
#pragma unroll
        for (int i = 0; i < 4; i++) {
            int e = tid + i * 256;
            int r = e >> 4, c4 = (e & 15) << 2;
            cp16(smem_u32(&Ksb[r * KS_STRIDE + c4]), kp + (size_t)(kk0 + r) * D_ + c4);
            cp16(smem_u32(&Vsb[r * VS_STRIDE + c4]), vp + (size_t)(kk0 + r) * D_ + c4);
        }
        if (tid < 4)
            cp16(smem_u32(Ms0 + s * 64 + tid * 16), maskp + kk0 + tid * 16);
    };

    const int qrow = q0 + wid * 16 + gid;

    // Q fragments (g_q already tf32-rounded + scaled)
    uint32_t qf[8][4];
#pragma unroll
    for (int kd = 0; kd < 8; kd++) {
        qf[kd][0] = __float_as_uint(qp[(size_t)qrow       * D_ + kd * 8 + tig]);
        qf[kd][1] = __float_as_uint(qp[(size_t)(qrow + 8) * D_ + kd * 8 + tig]);
        qf[kd][2] = __float_as_uint(qp[(size_t)qrow       * D_ + kd * 8 + tig + 4]);
        qf[kd][3] = __float_as_uint(qp[(size_t)(qrow + 8) * D_ + kd * 8 + tig + 4]);
    }
    const bool qm0 = maskp[qrow] != 0;
    const bool qm1 = maskp[qrow + 8] != 0;

    float m0 = -FLT_MAX, m1 = -FLT_MAX, l0 = 0.f, l1 = 0.f;
    float of[8][4];
#pragma unroll
    for (int df = 0; df < 8; df++)
#pragma unroll
        for (int q = 0; q < 4; q++) of[df][q] = 0.f;

    const float* bias0 = pos_bias + ((size_t)h * N_ + qrow) * N_;
    const float* bias1 = bias0 + 8 * (size_t)N_;

    float* prow0 = Ps + (wid * 16 + gid) * PS_STRIDE;
    float* prow1 = prow0 + 8 * PS_STRIDE;

    loadKV(0, 0);
    CP_COMMIT();

    for (int kt = 0; kt < N_ / 64; kt++) {
        const int kk0 = kt * 64;
        CP_WAIT0();
        __syncthreads();
        if (kt + 1 < N_ / 64) {
            loadKV((kt + 1) & 1, kk0 + 64);
            CP_COMMIT();
        }
        const float* Ksb = Ks0 + (kt & 1) * KS_ELEMS;
        const float* Vsb = Vs0 + (kt & 1) * VS_ELEMS;
        const unsigned char* Msb = Ms0 + (kt & 1) * 64;

        // S = Q @ K^T
        float sf[8][4];
#pragma unroll
        for (int ni = 0; ni < 8; ni++)
#pragma unroll
            for (int q = 0; q < 4; q++) sf[ni][q] = 0.f;

#pragma unroll
        for (int kd = 0; kd < 8; kd++) {
            uint32_t bfr[8][2];
#pragma unroll
            for (int ni = 0; ni < 8; ni++) {
                bfr[ni][0] = __float_as_uint(Ksb[(ni * 8 + gid) * KS_STRIDE + kd * 8 + tig]);
                bfr[ni][1] = __float_as_uint(Ksb[(ni * 8 + gid) * KS_STRIDE + kd * 8 + tig + 4]);
            }
#pragma unroll
            for (int ni = 0; ni < 8; ni++) mma8(sf[ni], qf[kd], bfr[ni]);
        }

        // bias (fp32, batched) + padding mask
        float2 bv0[8], bv1[8];
#pragma unroll
        for (int ni = 0; ni < 8; ni++) {
            bv0[ni] = *(const float2*)(bias0 + kk0 + ni * 8 + 2 * tig);
            bv1[ni] = *(const float2*)(bias1 + kk0 + ni * 8 + 2 * tig);
        }
        float mloc0 = -FLT_MAX, mloc1 = -FLT_MAX;
#pragma unroll
        for (int ni = 0; ni < 8; ni++) {
            bool km0 = Msb[ni * 8 + 2 * tig] != 0;
            bool km1 = Msb[ni * 8 + 2 * tig + 1] != 0;
            sf[ni][0] = (qm0 | km0) ? -FLT_MAX : sf[ni][0] + bv0[ni].x;
            sf[ni][1] = (qm0 | km1) ? -FLT_MAX : sf[ni][1] + bv0[ni].y;
            sf[ni][2] = (qm1 | km0) ? -FLT_MAX : sf[ni][2] + bv1[ni].x;
            sf[ni][3] = (qm1 | km1) ? -FLT_MAX : sf[ni][3] + bv1[ni].y;
            mloc0 = fmaxf(mloc0, fmaxf(sf[ni][0], sf[ni][1]));
            mloc1 = fmaxf(mloc1, fmaxf(sf[ni][2], sf[ni][3]));
        }
        mloc0 = fmaxf(mloc0, __shfl_xor_sync(0xffffffffu, mloc0, 1));
        mloc0 = fmaxf(mloc0, __shfl_xor_sync(0xffffffffu, mloc0, 2));
        mloc1 = fmaxf(mloc1, __shfl_xor_sync(0xffffffffu, mloc1, 1));
        mloc1 = fmaxf(mloc1, __shfl_xor_sync(0xffffffffu, mloc1, 2));

        float nm0 = fmaxf(m0, mloc0), nm1 = fmaxf(m1, mloc1);
        float a0 = fast_exp(m0 - nm0), a1 = fast_exp(m1 - nm1);
        m0 = nm0; m1 = nm1;

        float rs0 = 0.f, rs1 = 0.f;
#pragma unroll
        for (int ni = 0; ni < 8; ni++) {
            float p0 = fast_exp(sf[ni][0] - nm0);
            float p1 = fast_exp(sf[ni][1] - nm0);
            float p2 = fast_exp(sf[ni][2] - nm1);
            float p3 = fast_exp(sf[ni][3] - nm1);
            rs0 += p0 + p1; rs1 += p2 + p3;
            *(float2*)(prow0 + ni * 8 + 2 * tig) = make_float2(f2tff(p0), f2tff(p1));
            *(float2*)(prow1 + ni * 8 + 2 * tig) = make_float2(f2tff(p2), f2tff(p3));
        }
        rs0 += __shfl_xor_sync(0xffffffffu, rs0, 1);
        rs0 += __shfl_xor_sync(0xffffffffu, rs0, 2);
        rs1 += __shfl_xor_sync(0xffffffffu, rs1, 1);
        rs1 += __shfl_xor_sync(0xffffffffu, rs1, 2);
        l0 = l0 * a0 + rs0;
        l1 = l1 * a1 + rs1;

#pragma unroll
        for (int df = 0; df < 8; df++) {
            of[df][0] *= a0; of[df][1] *= a0;
            of[df][2] *= a1; of[df][3] *= a1;
        }
        __syncwarp();

        // O += P @ V
#pragma unroll
        for (int kk = 0; kk < 8; kk++) {
            uint32_t af[4];
            af[0] = __float_as_uint(prow0[kk * 8 + tig]);
            af[1] = __float_as_uint(prow1[kk * 8 + tig]);
            af[2] = __float_as_uint(prow0[kk * 8 + tig + 4]);
            af[3] = __float_as_uint(prow1[kk * 8 + tig + 4]);
#pragma unroll
            for (int df = 0; df < 8; df++) {
                uint32_t bfr[2];
                bfr[0] = __float_as_uint(Vsb[(kk * 8 + tig    ) * VS_STRIDE + df * 8 + gid]);
                bfr[1] = __float_as_uint(Vsb[(kk * 8 + tig + 4) * VS_STRIDE + df * 8 + gid]);
                mma8(of[df], af, bfr);
            }
        }
    }

    // Normalize; write tf32-rounded so out-proj can mma directly
    float inv0 = 1.f / l0, inv1 = 1.f / l1;
    float* op0 = g_att + ((size_t)(b * N_ + qrow))     * HD_ + h * D_;
    float* op1 = g_att + ((size_t)(b * N_ + qrow + 8)) * HD_ + h * D_;
#pragma unroll
    for (int df = 0; df < 8; df++) {
        *(float2*)(op0 + df * 8 + 2 * tig) =
            make_float2(f2tff(of[df][0] * inv0), f2tff(of[df][1] * inv0));
        *(float2*)(op1 + df * 8 + 2 * tig) =
            make_float2(f2tff(of[df][2] * inv1), f2tff(of[df][3] * inv1));
    }
}

// ---------------------------------------------------------------------------
// Launch
// ---------------------------------------------------------------------------
extern "C" void kernel_launch(void* const* d_in, const int* in_sizes, int n_in,
                              void* d_out, int out_size) {
    const float*         x        = (const float*)d_in[0];
    const float*         pos_bias = (const float*)d_in[1];
    const float*         Wqkv     = (const float*)d_in[2];
    const float*         Wout     = (const float*)d_in[3];
    const unsigned char* mask     = (const unsigned char*)d_in[4];
    float*               out      = (float*)d_out;

    float* xt;    cudaGetSymbolAddress((void**)&xt,    g_xt);
    float* wqkvt; cudaGetSymbolAddress((void**)&wqkvt, g_wqkvt);
    float* woutt; cudaGetSymbolAddress((void**)&woutt, g_woutt);

    // 0) pre-round operands to tf32(rna)
    round_tf32<<<1024, 256>>>(x,    xt,    (M_ * C_) / 4);
    round_tf32<<<1024, 256>>>(Wqkv, wqkvt, (C_ * QKVC_) / 4);
    round_tf32<<<1024, 256>>>(Wout, woutt, (HD_ * C_) / 4);

    // 1) QKV projection
    const int gemm_smem = (2 * AS_ELEMS + 2 * BS_ELEMS) * (int)sizeof(float);
    cudaFuncSetAttribute(gemm_tc<QKVC_, true>,
                         cudaFuncAttributeMaxDynamicSharedMemorySize, gemm_smem);
    gemm_tc<QKVC_, true><<<dim3(QKVC_ / 128, M_ / 128), 256, gemm_smem>>>(xt, wqkvt, nullptr);

    // 2) Flash attention
    cudaFuncSetAttribute(attn_tc,
                         cudaFuncAttributeMaxDynamicSharedMemorySize, ATTN_SMEM_BYTES);
    attn_tc<<<dim3(B_, N_ / 128, H_), 256, ATTN_SMEM_BYTES>>>(pos_bias, mask);

    // 3) Output projection
    cudaFuncSetAttribute(gemm_tc<HD_, false>,
                         cudaFuncAttributeMaxDynamicSharedMemorySize, gemm_smem);
    gemm_tc<HD_, false><<<dim3(HD_ / 128, M_ / 128), 256, gemm_smem>>>(nullptr, woutt, out);
}

// round 5
// speedup vs baseline: 3.8124x; 1.0000x over previous
#include <cuda_runtime.h>
#include <math.h>
#include <float.h>
#include <stdint.h>

// Problem constants (B,N,C,H,D) = (2, 2048, 1024, 16, 64)
#define B_    2
#define N_    2048
#define C_    1024
#define H_    16
#define D_    64
#define HD_   1024
#define QKVC_ 3072
#define M_    (B_*N_)
#define SCALE_ 0.125f

// Scratch (__device__ globals; no allocation allowed)
__device__ float g_q[(size_t)B_*H_*N_*D_];
__device__ float g_k[(size_t)B_*H_*N_*D_];
__device__ float g_v[(size_t)B_*H_*N_*D_];
__device__ float g_att[(size_t)M_*HD_];
__device__ float g_xt[(size_t)M_*C_];        // tf32-rounded x
__device__ float g_wqkvt[(size_t)C_*QKVC_];  // tf32-rounded Wqkv
__device__ float g_woutt[(size_t)HD_*C_];    // tf32-rounded Wout

// ---------------------------------------------------------------------------
// helpers
// ---------------------------------------------------------------------------
__device__ __forceinline__ uint32_t f2tf(float x) {
    uint32_t r;
    asm("cvt.rna.tf32.f32 %0, %1;" : "=r"(r) : "f"(x));
    return r;
}
__device__ __forceinline__ float f2tff(float x) { return __uint_as_float(f2tf(x)); }

__device__ __forceinline__ void mma8(float c[4], const uint32_t a[4], const uint32_t b[2]) {
    asm volatile("mma.sync.aligned.m16n8k8.row.col.f32.tf32.tf32.f32 "
        "{%0,%1,%2,%3},{%4,%5,%6,%7},{%8,%9},{%0,%1,%2,%3};"
        : "+f"(c[0]), "+f"(c[1]), "+f"(c[2]), "+f"(c[3])
        : "r"(a[0]), "r"(a[1]), "r"(a[2]), "r"(a[3]), "r"(b[0]), "r"(b[1]));
}

__device__ __forceinline__ uint32_t smem_u32(const void* p) {
    return (uint32_t)__cvta_generic_to_shared(p);
}
__device__ __forceinline__ void cp16(uint32_t dst, const void* src) {
    asm volatile("cp.async.cg.shared.global [%0], [%1], 16;" :: "r"(dst), "l"(src));
}
#define CP_COMMIT() asm volatile("cp.async.commit_group;" ::: "memory")
#define CP_WAIT0()  asm volatile("cp.async.wait_group 0;" ::: "memory")

// FMA-pipe exp (deg-5 poly 2^f, ~3e-6 rel)
__device__ __forceinline__ float fast_exp(float x) {
    float y = x * 1.4426950408889634f;
    y = fmaxf(y, -126.0f);
    float r = rintf(y);
    float f = y - r;
    float p = 1.3333558146e-3f;
    p = fmaf(p, f, 9.6181291076e-3f);
    p = fmaf(p, f, 5.5504108665e-2f);
    p = fmaf(p, f, 2.4022650696e-1f);
    p = fmaf(p, f, 6.9314718056e-1f);
    p = fmaf(p, f, 1.0f);
    return p * __int_as_float(((int)r + 127) << 23);
}

// ---------------------------------------------------------------------------
// Prep: round fp32 -> tf32(rna) stored as fp32 (grid-stride over float4)
// ---------------------------------------------------------------------------
__global__ void round_tf32(const float* __restrict__ in, float* __restrict__ out, int n4) {
    int i = blockIdx.x * blockDim.x + threadIdx.x;
    int stride = gridDim.x * blockDim.x;
    for (; i < n4; i += stride) {
        float4 v = ((const float4*)in)[i];
        ((float4*)out)[i] = make_float4(f2tff(v.x), f2tff(v.y), f2tff(v.z), f2tff(v.w));
    }
}

// ---------------------------------------------------------------------------
// tf32 TC GEMM, cp.async 2-stage pipeline. Inputs pre-rounded (no in-loop cvt).
// 128x128 tile, BK=32, 8 warps (4m x 2n).
// ---------------------------------------------------------------------------
#define AS_ELEMS 4608    // 128*36
#define BS_ELEMS 4352    // 32*136

template<int NC, bool IS_QKV>
__global__ void __launch_bounds__(256, 2) gemm_tc(const float* __restrict__ A_,
                                                  const float* __restrict__ W,
                                                  float* __restrict__ out) {
    extern __shared__ float sg[];
    float* As0 = sg;                  // 2 stages of [128][36]
    float* Bs0 = sg + 2 * AS_ELEMS;   // 2 stages of [32][136]

    const float* A = IS_QKV ? A_ : (const float*)g_att;

    const int tid  = threadIdx.x;
    const int lane = tid & 31, warp = tid >> 5;
    const int gid  = lane >> 2, tig = lane & 3;
    const int wm   = warp & 3, wn = warp >> 2;
    const int bm   = blockIdx.y * 128, bn = blockIdx.x * 128;

    auto load_tiles = [&](int s, int k0) {
        float* As = As0 + s * AS_ELEMS;
        float* Bs = Bs0 + s * BS_ELEMS;
#pragma unroll
        for (int i = 0; i < 4; i++) {
            int e  = tid + i * 256;
            int m  = (e & 7) | ((e >> 3) & 0x78);
            int kq = ((e >> 3) & 7) << 2;
            cp16(smem_u32(&As[m * 36 + kq]), A + (size_t)(bm + m) * 1024 + k0 + kq);
        }
#pragma unroll
        for (int i = 0; i < 4; i++) {
            int e  = tid + i * 256;
            int k  = e >> 5;
            int n4 = (e & 31) << 2;
            cp16(smem_u32(&Bs[k * 136 + n4]), W + (size_t)(k0 + k) * NC + bn + n4);
        }
    };

    float acc[2][8][4];
#pragma unroll
    for (int mi = 0; mi < 2; mi++)
#pragma unroll
        for (int ni = 0; ni < 8; ni++)
#pragma unroll
            for (int q = 0; q < 4; q++) acc[mi][ni][q] = 0.f;

    load_tiles(0, 0);
    CP_COMMIT();

    for (int it = 0; it < 32; it++) {
        CP_WAIT0();
        __syncthreads();
        if (it + 1 < 32) {
            load_tiles((it + 1) & 1, (it + 1) * 32);
            CP_COMMIT();
        }
        float* As = As0 + (it & 1) * AS_ELEMS;
        float* Bs = Bs0 + (it & 1) * BS_ELEMS;

#pragma unroll
        for (int kk = 0; kk < 32; kk += 8) {
            uint32_t af[2][4];
#pragma unroll
            for (int mi = 0; mi < 2; mi++) {
                int r0 = wm * 32 + mi * 16 + gid;
                af[mi][0] = __float_as_uint(As[(r0    ) * 36 + kk + tig]);
                af[mi][1] = __float_as_uint(As[(r0 + 8) * 36 + kk + tig]);
                af[mi][2] = __float_as_uint(As[(r0    ) * 36 + kk + tig + 4]);
                af[mi][3] = __float_as_uint(As[(r0 + 8) * 36 + kk + tig + 4]);
            }
#pragma unroll
            for (int ni = 0; ni < 8; ni++) {
                uint32_t bf[2];
                int cc = wn * 64 + ni * 8 + gid;
                bf[0] = __float_as_uint(Bs[(kk + tig    ) * 136 + cc]);
                bf[1] = __float_as_uint(Bs[(kk + tig + 4) * 136 + cc]);
                mma8(acc[0][ni], af[0], bf);
                mma8(acc[1][ni], af[1], bf);
            }
        }
        __syncthreads();
    }

    if (IS_QKV) {
        // c = h*192 + d*3 + s; q pre-scaled; all outputs tf32-rounded at store
#pragma unroll
        for (int mi = 0; mi < 2; mi++)
#pragma unroll
            for (int ni = 0; ni < 8; ni++)
#pragma unroll
                for (int q = 0; q < 4; q++) {
                    int r = bm + wm * 32 + mi * 16 + gid + ((q >= 2) ? 8 : 0);
                    int c = bn + wn * 64 + ni * 8 + 2 * tig + (q & 1);
                    int bb = r >> 11, n = r & 2047;
                    int s  = c % 3,   hd = c / 3;
                    int d  = hd & 63, h = hd >> 6;
                    size_t idx = ((size_t)((bb * H_ + h) * N_ + n)) * D_ + d;
                    float val = acc[mi][ni][q];
                    if (s == 0)      g_q[idx] = f2tff(val * SCALE_);
                    else if (s == 1) g_k[idx] = f2tff(val);
                    else             g_v[idx] = f2tff(val);
                }
    } else {
#pragma unroll
        for (int mi = 0; mi < 2; mi++)
#pragma unroll
            for (int ni = 0; ni < 8; ni++) {
                int r = bm + wm * 32 + mi * 16 + gid;
                int c = bn + wn * 64 + ni * 8 + 2 * tig;
                *(float2*)(out + (size_t)r * NC + c) =
                    make_float2(acc[mi][ni][0], acc[mi][ni][1]);
                *(float2*)(out + (size_t)(r + 8) * NC + c) =
                    make_float2(acc[mi][ni][2], acc[mi][ni][3]);
            }
    }
}

// ---------------------------------------------------------------------------
// Flash attention, tf32 TC, cp.async double-buffered K/V (pre-rounded).
// ---------------------------------------------------------------------------
#define KS_STRIDE 68
#define VS_STRIDE 72
#define PS_STRIDE 68
#define KS_ELEMS (64*KS_STRIDE)   // 4352
#define VS_ELEMS (64*VS_STRIDE)   // 4608
#define PS_ELEMS (128*PS_STRIDE)  // 8704
// smem: 2*KS + 2*VS + PS floats, then 2x64B mask
#define ATTN_SMEM_FLOATS (2*KS_ELEMS + 2*VS_ELEMS + PS_ELEMS)
#define ATTN_SMEM_BYTES  (ATTN_SMEM_FLOATS*4 + 128)

__global__ void __launch_bounds__(256, 2) attn_tc(const float* __restrict__ pos_bias,
                                                  const unsigned char* __restrict__ mask) {
    extern __shared__ float smv[];
    float* Ks0 = smv;                        // 2 x [64][68]
    float* Vs0 = smv + 2 * KS_ELEMS;         // 2 x [64][72]
    float* Ps  = smv + 2 * KS_ELEMS + 2 * VS_ELEMS;  // [128][68]
    unsigned char* Ms0 = (unsigned char*)(Ps + PS_ELEMS);  // 2 x [64]

    const int tid  = threadIdx.x;
    const int lane = tid & 31, wid = tid >> 5;
    const int gid  = lane >> 2, tig = lane & 3;
    const int b  = blockIdx.x;
    const int q0 = blockIdx.y * 128;
    const int h  = blockIdx.z;
    const int bh = b * H_ + h;

    const float* qp = g_q + (size_t)bh * N_ * D_;
    const float* kp = g_k + (size_t)bh * N_ * D_;
    const float* vp = g_v + (size_t)bh * N_ * D_;
    const unsigned char* maskp = mask + (size_t)b * N_;

    auto loadKV = [&](int s, int kk0) {
        float* Ksb = Ks0 + s * KS_ELEMS;
        float* Vsb = Vs0 + s * VS_ELEMS;
#pragma unroll
        for (int i = 0; i < 4; i++) {
            int e = tid + i * 256;
            int r = e >> 4, c4 = (e & 15) << 2;
            cp16(smem_u32(&Ksb[r * KS_STRIDE + c4]), kp + (size_t)(kk0 + r) * D_ + c4);
            cp16(smem_u32(&Vsb[r * VS_STRIDE + c4]), vp + (size_t)(kk0 + r) * D_ + c4);
        }
        if (tid < 4)
            cp16(smem_u32(Ms0 + s * 64 + tid * 16), maskp + kk0 + tid * 16);
    };

    const int qrow = q0 + wid * 16 + gid;

    // Q fragments (g_q already tf32-rounded + scaled)
    uint32_t qf[8][4];
#pragma unroll
    for (int kd = 0; kd < 8; kd++) {
        qf[kd][0] = __float_as_uint(qp[(size_t)qrow       * D_ + kd * 8 + tig]);
        qf[kd][1] = __float_as_uint(qp[(size_t)(qrow + 8) * D_ + kd * 8 + tig]);
        qf[kd][2] = __float_as_uint(qp[(size_t)qrow       * D_ + kd * 8 + tig + 4]);
        qf[kd][3] = __float_as_uint(qp[(size_t)(qrow + 8) * D_ + kd * 8 + tig + 4]);
    }
    const bool qm0 = maskp[qrow] != 0;
    const bool qm1 = maskp[qrow + 8] != 0;

    float m0 = -FLT_MAX, m1 = -FLT_MAX, l0 = 0.f, l1 = 0.f;
    float of[8][4];
#pragma unroll
    for (int df = 0; df < 8; df++)
#pragma unroll
        for (int q = 0; q < 4; q++) of[df][q] = 0.f;

    const float* bias0 = pos_bias + ((size_t)h * N_ + qrow) * N_;
    const float* bias1 = bias0 + 8 * (size_t)N_;

    float* prow0 = Ps + (wid * 16 + gid) * PS_STRIDE;
    float* prow1 = prow0 + 8 * PS_STRIDE;

    loadKV(0, 0);
    CP_COMMIT();

    for (int kt = 0; kt < N_ / 64; kt++) {
        const int kk0 = kt * 64;
        CP_WAIT0();
        __syncthreads();
        if (kt + 1 < N_ / 64) {
            loadKV((kt + 1) & 1, kk0 + 64);
            CP_COMMIT();
        }
        const float* Ksb = Ks0 + (kt & 1) * KS_ELEMS;
        const float* Vsb = Vs0 + (kt & 1) * VS_ELEMS;
        const unsigned char* Msb = Ms0 + (kt & 1) * 64;

        // S = Q @ K^T
        float sf[8][4];
#pragma unroll
        for (int ni = 0; ni < 8; ni++)
#pragma unroll
            for (int q = 0; q < 4; q++) sf[ni][q] = 0.f;

#pragma unroll
        for (int kd = 0; kd < 8; kd++) {
            uint32_t bfr[8][2];
#pragma unroll
            for (int ni = 0; ni < 8; ni++) {
                bfr[ni][0] = __float_as_uint(Ksb[(ni * 8 + gid) * KS_STRIDE + kd * 8 + tig]);
                bfr[ni][1] = __float_as_uint(Ksb[(ni * 8 + gid) * KS_STRIDE + kd * 8 + tig + 4]);
            }
#pragma unroll
            for (int ni = 0; ni < 8; ni++) mma8(sf[ni], qf[kd], bfr[ni]);
        }

        // bias (fp32, batched) + padding mask
        float2 bv0[8], bv1[8];
#pragma unroll
        for (int ni = 0; ni < 8; ni++) {
            bv0[ni] = *(const float2*)(bias0 + kk0 + ni * 8 + 2 * tig);
            bv1[ni] = *(const float2*)(bias1 + kk0 + ni * 8 + 2 * tig);
        }
        float mloc0 = -FLT_MAX, mloc1 = -FLT_MAX;
#pragma unroll
        for (int ni = 0; ni < 8; ni++) {
            bool km0 = Msb[ni * 8 + 2 * tig] != 0;
            bool km1 = Msb[ni * 8 + 2 * tig + 1] != 0;
            sf[ni][0] = (qm0 | km0) ? -FLT_MAX : sf[ni][0] + bv0[ni].x;
            sf[ni][1] = (qm0 | km1) ? -FLT_MAX : sf[ni][1] + bv0[ni].y;
            sf[ni][2] = (qm1 | km0) ? -FLT_MAX : sf[ni][2] + bv1[ni].x;
            sf[ni][3] = (qm1 | km1) ? -FLT_MAX : sf[ni][3] + bv1[ni].y;
            mloc0 = fmaxf(mloc0, fmaxf(sf[ni][0], sf[ni][1]));
            mloc1 = fmaxf(mloc1, fmaxf(sf[ni][2], sf[ni][3]));
        }
        mloc0 = fmaxf(mloc0, __shfl_xor_sync(0xffffffffu, mloc0, 1));
        mloc0 = fmaxf(mloc0, __shfl_xor_sync(0xffffffffu, mloc0, 2));
        mloc1 = fmaxf(mloc1, __shfl_xor_sync(0xffffffffu, mloc1, 1));
        mloc1 = fmaxf(mloc1, __shfl_xor_sync(0xffffffffu, mloc1, 2));

        float nm0 = fmaxf(m0, mloc0), nm1 = fmaxf(m1, mloc1);
        float a0 = fast_exp(m0 - nm0), a1 = fast_exp(m1 - nm1);
        m0 = nm0; m1 = nm1;

        float rs0 = 0.f, rs1 = 0.f;
#pragma unroll
        for (int ni = 0; ni < 8; ni++) {
            float p0 = fast_exp(sf[ni][0] - nm0);
            float p1 = fast_exp(sf[ni][1] - nm0);
            float p2 = fast_exp(sf[ni][2] - nm1);
            float p3 = fast_exp(sf[ni][3] - nm1);
            rs0 += p0 + p1; rs1 += p2 + p3;
            *(float2*)(prow0 + ni * 8 + 2 * tig) = make_float2(f2tff(p0), f2tff(p1));
            *(float2*)(prow1 + ni * 8 + 2 * tig) = make_float2(f2tff(p2), f2tff(p3));
        }
        rs0 += __shfl_xor_sync(0xffffffffu, rs0, 1);
        rs0 += __shfl_xor_sync(0xffffffffu, rs0, 2);
        rs1 += __shfl_xor_sync(0xffffffffu, rs1, 1);
        rs1 += __shfl_xor_sync(0xffffffffu, rs1, 2);
        l0 = l0 * a0 + rs0;
        l1 = l1 * a1 + rs1;

#pragma unroll
        for (int df = 0; df < 8; df++) {
            of[df][0] *= a0; of[df][1] *= a0;
            of[df][2] *= a1; of[df][3] *= a1;
        }
        __syncwarp();

        // O += P @ V
#pragma unroll
        for (int kk = 0; kk < 8; kk++) {
            uint32_t af[4];
            af[0] = __float_as_uint(prow0[kk * 8 + tig]);
            af[1] = __float_as_uint(prow1[kk * 8 + tig]);
            af[2] = __float_as_uint(prow0[kk * 8 + tig + 4]);
            af[3] = __float_as_uint(prow1[kk * 8 + tig + 4]);
#pragma unroll
            for (int df = 0; df < 8; df++) {
                uint32_t bfr[2];
                bfr[0] = __float_as_uint(Vsb[(kk * 8 + tig    ) * VS_STRIDE + df * 8 + gid]);
                bfr[1] = __float_as_uint(Vsb[(kk * 8 + tig + 4) * VS_STRIDE + df * 8 + gid]);
                mma8(of[df], af, bfr);
            }
        }
    }

    // Normalize; write tf32-rounded so out-proj can mma directly
    float inv0 = 1.f / l0, inv1 = 1.f / l1;
    float* op0 = g_att + ((size_t)(b * N_ + qrow))     * HD_ + h * D_;
    float* op1 = g_att + ((size_t)(b * N_ + qrow + 8)) * HD_ + h * D_;
#pragma unroll
    for (int df = 0; df < 8; df++) {
        *(float2*)(op0 + df * 8 + 2 * tig) =
            make_float2(f2tff(of[df][0] * inv0), f2tff(of[df][1] * inv0));
        *(float2*)(op1 + df * 8 + 2 * tig) =
            make_float2(f2tff(of[df][2] * inv1), f2tff(of[df][3] * inv1));
    }
}

// ---------------------------------------------------------------------------
// Launch
// ---------------------------------------------------------------------------
extern "C" void kernel_launch(void* const* d_in, const int* in_sizes, int n_in,
                              void* d_out, int out_size) {
    const float*         x        = (const float*)d_in[0];
    const float*         pos_bias = (const float*)d_in[1];
    const float*         Wqkv     = (const float*)d_in[2];
    const float*         Wout     = (const float*)d_in[3];
    const unsigned char* mask     = (const unsigned char*)d_in[4];
    float*               out      = (float*)d_out;

    float* xt;    cudaGetSymbolAddress((void**)&xt,    g_xt);
    float* wqkvt; cudaGetSymbolAddress((void**)&wqkvt, g_wqkvt);
    float* woutt; cudaGetSymbolAddress((void**)&woutt, g_woutt);

    // 0) pre-round operands to tf32(rna)
    round_tf32<<<1024, 256>>>(x,    xt,    (M_ * C_) / 4);
    round_tf32<<<1024, 256>>>(Wqkv, wqkvt, (C_ * QKVC_) / 4);
    round_tf32<<<1024, 256>>>(Wout, woutt, (HD_ * C_) / 4);

    // 1) QKV projection
    const int gemm_smem = (2 * AS_ELEMS + 2 * BS_ELEMS) * (int)sizeof(float);
    cudaFuncSetAttribute(gemm_tc<QKVC_, true>,
                         cudaFuncAttributeMaxDynamicSharedMemorySize, gemm_smem);
    gemm_tc<QKVC_, true><<<dim3(QKVC_ / 128, M_ / 128), 256, gemm_smem>>>(xt, wqkvt, nullptr);

    // 2) Flash attention
    cudaFuncSetAttribute(attn_tc,
                         cudaFuncAttributeMaxDynamicSharedMemorySize, ATTN_SMEM_BYTES);
    attn_tc<<<dim3(B_, N_ / 128, H_), 256, ATTN_SMEM_BYTES>>>(pos_bias, mask);

    // 3) Output projection
    cudaFuncSetAttribute(gemm_tc<HD_, false>,
                         cudaFuncAttributeMaxDynamicSharedMemorySize, gemm_smem);
    gemm_tc<HD_, false><<<dim3(HD_ / 128, M_ / 128), 256, gemm_smem>>>(nullptr, woutt, out);
}

// round 7
// speedup vs baseline: 5.6954x; 1.4939x over previous
#include <cuda_runtime.h>
#include <cuda_fp16.h>
#include <math.h>
#include <float.h>
#include <stdint.h>

#define B_    2
#define N_    2048
#define C_    1024
#define H_    16
#define D_    64
#define HD_   1024
#define QKVC_ 3072
#define M_    (B_*N_)
#define SCALE_ 0.125f

// Scratch (__device__ globals). v stored transposed: [B,H,D,N].
__device__ __half g_q[(size_t)B_*H_*N_*D_];
__device__ __half g_k[(size_t)B_*H_*N_*D_];
__device__ __half g_v[(size_t)B_*H_*D_*N_];
__device__ __half g_att[(size_t)M_*HD_];
__device__ __half g_xh[(size_t)M_*C_];
__device__ __half g_wqkvt[(size_t)QKVC_*C_];   // Wqkv^T [3072][1024]
__device__ __half g_woutt[(size_t)HD_*HD_];    // Wout^T [1024][1024]

// ---------------------------------------------------------------------------
__device__ __forceinline__ void mma16(float c[4], const uint32_t a[4], const uint32_t b[2]) {
    asm volatile("mma.sync.aligned.m16n8k16.row.col.f32.f16.f16.f32 "
        "{%0,%1,%2,%3},{%4,%5,%6,%7},{%8,%9},{%0,%1,%2,%3};"
        : "+f"(c[0]), "+f"(c[1]), "+f"(c[2]), "+f"(c[3])
        : "r"(a[0]), "r"(a[1]), "r"(a[2]), "r"(a[3]), "r"(b[0]), "r"(b[1]));
}
__device__ __forceinline__ uint32_t smem_u32(const void* p) {
    return (uint32_t)__cvta_generic_to_shared(p);
}
__device__ __forceinline__ void cp16(uint32_t dst, const void* src) {
    asm volatile("cp.async.cg.shared.global [%0], [%1], 16;" :: "r"(dst), "l"(src));
}
#define CP_COMMIT() asm volatile("cp.async.commit_group;" ::: "memory")
#define CP_WAIT0()  asm volatile("cp.async.wait_group 0;" ::: "memory")

__device__ __forceinline__ float fast_exp(float x) {
    float y = x * 1.4426950408889634f;
    y = fmaxf(y, -126.0f);
    float r = rintf(y);
    float f = y - r;
    float p = 1.3333558146e-3f;
    p = fmaf(p, f, 9.6181291076e-3f);
    p = fmaf(p, f, 5.5504108665e-2f);
    p = fmaf(p, f, 2.4022650696e-1f);
    p = fmaf(p, f, 6.9314718056e-1f);
    p = fmaf(p, f, 1.0f);
    return p * __int_as_float(((int)r + 127) << 23);
}

// ---------------------------------------------------------------------------
// Prep kernels
// ---------------------------------------------------------------------------
__global__ void conv_half(const float* __restrict__ in, __half* __restrict__ out, int n4) {
    int i = blockIdx.x * blockDim.x + threadIdx.x;
    int st = gridDim.x * blockDim.x;
    for (; i < n4; i += st) {
        float4 v = ((const float4*)in)[i];
        ((__half2*)out)[2*i]   = __floats2half2_rn(v.x, v.y);
        ((__half2*)out)[2*i+1] = __floats2half2_rn(v.z, v.w);
    }
}
// out[n][k] = half(in[k][n]); in is [K][N] row-major
__global__ void transpose_half(const float* __restrict__ in, __half* __restrict__ out,
                               int K, int N) {
    __shared__ float t[32][33];
    int bx = blockIdx.x * 32, by = blockIdx.y * 32;
    int tx = threadIdx.x, ty = threadIdx.y;
#pragma unroll
    for (int i = 0; i < 4; i++)
        t[ty + i * 8][tx] = in[(size_t)(by + ty + i * 8) * N + bx + tx];
    __syncthreads();
#pragma unroll
    for (int i = 0; i < 4; i++)
        out[(size_t)(bx + ty + i * 8) * K + by + tx] = __float2half_rn(t[tx][ty + i * 8]);
}

// ---------------------------------------------------------------------------
// fp16 TC GEMM: out[M x NC] = A[M x 1024] @ Bt[NC x 1024]^T
// 128x128 tile, BK=32, 8 warps (4m x 2n), 2-stage cp.async, m16n8k16.
// Smem rows stride 40 halves -> fully conflict-free fragment LDS.
// ---------------------------------------------------------------------------
#define GS 40            // half stride
#define GT_ELEMS (128*GS)

template<int NC, bool IS_QKV>
__global__ void __launch_bounds__(256, 2) gemm_h(const __half* __restrict__ A,
                                                 const __half* __restrict__ Bt,
                                                 float* __restrict__ out) {
    __shared__ __half As[2][GT_ELEMS];
    __shared__ __half Bs[2][GT_ELEMS];

    const int tid  = threadIdx.x;
    const int lane = tid & 31, warp = tid >> 5;
    const int gid  = lane >> 2, tig = lane & 3;
    const int wm   = warp & 3, wn = warp >> 2;
    const int bm   = blockIdx.y * 128, bn = blockIdx.x * 128;

    const __half* Ab = A  + (size_t)bm * 1024;
    const __half* Bb = Bt + (size_t)bn * 1024;

    auto load_tiles = [&](int s, int k0) {
#pragma unroll
        for (int i = 0; i < 2; i++) {
            int e = tid + i * 256;          // 0..511
            int row = e >> 2, o8 = (e & 3) * 8;
            cp16(smem_u32(&As[s][row * GS + o8]), Ab + (size_t)row * 1024 + k0 + o8);
            cp16(smem_u32(&Bs[s][row * GS + o8]), Bb + (size_t)row * 1024 + k0 + o8);
        }
    };

    float acc[2][8][4];
#pragma unroll
    for (int mi = 0; mi < 2; mi++)
#pragma unroll
        for (int ni = 0; ni < 8; ni++)
#pragma unroll
            for (int q = 0; q < 4; q++) acc[mi][ni][q] = 0.f;

    load_tiles(0, 0);
    CP_COMMIT();

    for (int it = 0; it < 32; it++) {
        CP_WAIT0();
        __syncthreads();
        if (it + 1 < 32) { load_tiles((it + 1) & 1, (it + 1) * 32); CP_COMMIT(); }
        const __half* Asb = As[it & 1];
        const __half* Bsb = Bs[it & 1];

#pragma unroll
        for (int kk = 0; kk < 32; kk += 16) {
            uint32_t af[2][4];
#pragma unroll
            for (int mi = 0; mi < 2; mi++) {
                int r0 = wm * 32 + mi * 16 + gid;
                af[mi][0] = *(const uint32_t*)&Asb[(r0    ) * GS + kk + 2 * tig];
                af[mi][1] = *(const uint32_t*)&Asb[(r0 + 8) * GS + kk + 2 * tig];
                af[mi][2] = *(const uint32_t*)&Asb[(r0    ) * GS + kk + 2 * tig + 8];
                af[mi][3] = *(const uint32_t*)&Asb[(r0 + 8) * GS + kk + 2 * tig + 8];
            }
#pragma unroll
            for (int ni = 0; ni < 8; ni++) {
                int cc = wn * 64 + ni * 8 + gid;
                uint32_t bf[2];
                bf[0] = *(const uint32_t*)&Bsb[cc * GS + kk + 2 * tig];
                bf[1] = *(const uint32_t*)&Bsb[cc * GS + kk + 2 * tig + 8];
                mma16(acc[0][ni], af[0], bf);
                mma16(acc[1][ni], af[1], bf);
            }
        }
        __syncthreads();
    }

    if (IS_QKV) {
        // c = h*192 + d*3 + s; q pre-scaled; v transposed [B,H,D,N]
#pragma unroll
        for (int mi = 0; mi < 2; mi++)
#pragma unroll
            for (int ni = 0; ni < 8; ni++)
#pragma unroll
                for (int q = 0; q < 4; q++) {
                    int r = bm + wm * 32 + mi * 16 + gid + ((q >= 2) ? 8 : 0);
                    int c = bn + wn * 64 + ni * 8 + 2 * tig + (q & 1);
                    int bb = r >> 11, n = r & 2047;
                    int s  = c % 3,   hd = c / 3;
                    int d  = hd & 63, h = hd >> 6;
                    float val = acc[mi][ni][q];
                    if (s == 0)
                        g_q[((size_t)((bb * H_ + h) * N_ + n)) * D_ + d] =
                            __float2half_rn(val * SCALE_);
                    else if (s == 1)
                        g_k[((size_t)((bb * H_ + h) * N_ + n)) * D_ + d] =
                            __float2half_rn(val);
                    else
                        g_v[((size_t)((bb * H_ + h) * D_ + d)) * N_ + n] =
                            __float2half_rn(val);
                }
    } else {
#pragma unroll
        for (int mi = 0; mi < 2; mi++)
#pragma unroll
            for (int ni = 0; ni < 8; ni++) {
                int r = bm + wm * 32 + mi * 16 + gid;
                int c = bn + wn * 64 + ni * 8 + 2 * tig;
                *(float2*)(out + (size_t)r * NC + c) =
                    make_float2(acc[mi][ni][0], acc[mi][ni][1]);
                *(float2*)(out + (size_t)(r + 8) * NC + c) =
                    make_float2(acc[mi][ni][2], acc[mi][ni][3]);
            }
    }
}

// ---------------------------------------------------------------------------
// Flash attention, fp16 mma. K tile [key][d], V tile [d][key] (from g_v),
// P as half2. Strides 72 halves -> conflict-free 32-bit fragment LDS.
// ---------------------------------------------------------------------------
#define KS_H 72
#define VT_H 72
#define PS_H 72
#define KS_E (64*KS_H)
#define VT_E (64*VT_H)
#define PS_E (128*PS_H)
#define ATTN_SMEM_BYTES ((2*KS_E + 2*VT_E + PS_E)*2 + 128)

__global__ void __launch_bounds__(256, 2) attn_h(const float* __restrict__ pos_bias,
                                                 const unsigned char* __restrict__ mask) {
    extern __shared__ __half smh[];
    __half* Ks0 = smh;
    __half* Vt0 = smh + 2 * KS_E;
    __half* Ps  = smh + 2 * KS_E + 2 * VT_E;
    unsigned char* Ms0 = (unsigned char*)(Ps + PS_E);

    const int tid = threadIdx.x, lane = tid & 31, wid = tid >> 5;
    const int gid = lane >> 2, tig = lane & 3;
    const int b = blockIdx.x, q0 = blockIdx.y * 128, h = blockIdx.z;
    const int bh = b * H_ + h;

    const __half* qp = g_q + (size_t)bh * N_ * D_;
    const __half* kp = g_k + (size_t)bh * N_ * D_;
    const __half* vp = g_v + (size_t)bh * D_ * N_;   // [d][n]
    const unsigned char* maskp = mask + (size_t)b * N_;

    auto loadKV = [&](int s, int kk0) {
        __half* Ksb = Ks0 + s * KS_E;
        __half* Vtb = Vt0 + s * VT_E;
#pragma unroll
        for (int i = 0; i < 2; i++) {
            int e = tid + i * 256;          // 0..511
            int row = e >> 3, o8 = (e & 7) * 8;
            cp16(smem_u32(&Ksb[row * KS_H + o8]), kp + (size_t)(kk0 + row) * D_ + o8);
            cp16(smem_u32(&Vtb[row * VT_H + o8]), vp + (size_t)row * N_ + kk0 + o8);
        }
        if (tid < 4)
            cp16(smem_u32(Ms0 + s * 64 + tid * 16), maskp + kk0 + tid * 16);
    };

    const int qrow = q0 + wid * 16 + gid;
    const __half* qh0 = qp + (size_t)qrow * D_;
    const __half* qh1 = qh0 + 8 * D_;

    uint32_t qf[4][4];
#pragma unroll
    for (int kd = 0; kd < 4; kd++) {
        qf[kd][0] = *(const uint32_t*)(qh0 + kd * 16 + 2 * tig);
        qf[kd][1] = *(const uint32_t*)(qh1 + kd * 16 + 2 * tig);
        qf[kd][2] = *(const uint32_t*)(qh0 + kd * 16 + 2 * tig + 8);
        qf[kd][3] = *(const uint32_t*)(qh1 + kd * 16 + 2 * tig + 8);
    }
    const bool qm0 = maskp[qrow] != 0, qm1 = maskp[qrow + 8] != 0;

    float m0 = -FLT_MAX, m1 = -FLT_MAX, l0 = 0.f, l1 = 0.f;
    float of[8][4];
#pragma unroll
    for (int df = 0; df < 8; df++)
#pragma unroll
        for (int q = 0; q < 4; q++) of[df][q] = 0.f;

    const float* bias0 = pos_bias + ((size_t)h * N_ + qrow) * N_;
    const float* bias1 = bias0 + 8 * (size_t)N_;
    __half* prow0 = Ps + (wid * 16 + gid) * PS_H;
    __half* prow1 = prow0 + 8 * PS_H;

    loadKV(0, 0);
    CP_COMMIT();

    for (int kt = 0; kt < N_ / 64; kt++) {
        const int kk0 = kt * 64;
        CP_WAIT0();
        __syncthreads();
        if (kt + 1 < N_ / 64) { loadKV((kt + 1) & 1, kk0 + 64); CP_COMMIT(); }
        const __half* Ksb = Ks0 + (kt & 1) * KS_E;
        const __half* Vtb = Vt0 + (kt & 1) * VT_E;
        const unsigned char* Msb = Ms0 + (kt & 1) * 64;

        // bias prefetch (DRAM latency overlaps S mma)
        float2 bv0[8], bv1[8];
#pragma unroll
        for (int ni = 0; ni < 8; ni++) {
            bv0[ni] = *(const float2*)(bias0 + kk0 + ni * 8 + 2 * tig);
            bv1[ni] = *(const float2*)(bias1 + kk0 + ni * 8 + 2 * tig);
        }

        // S = Q @ K^T
        float sf[8][4];
#pragma unroll
        for (int ni = 0; ni < 8; ni++)
#pragma unroll
            for (int q = 0; q < 4; q++) sf[ni][q] = 0.f;
#pragma unroll
        for (int kd = 0; kd < 4; kd++) {
            uint32_t bfr[8][2];
#pragma unroll
            for (int ni = 0; ni < 8; ni++) {
                bfr[ni][0] = *(const uint32_t*)&Ksb[(ni * 8 + gid) * KS_H + kd * 16 + 2 * tig];
                bfr[ni][1] = *(const uint32_t*)&Ksb[(ni * 8 + gid) * KS_H + kd * 16 + 2 * tig + 8];
            }
#pragma unroll
            for (int ni = 0; ni < 8; ni++) mma16(sf[ni], qf[kd], bfr[ni]);
        }

        float mloc0 = -FLT_MAX, mloc1 = -FLT_MAX;
#pragma unroll
        for (int ni = 0; ni < 8; ni++) {
            bool km0 = Msb[ni * 8 + 2 * tig] != 0;
            bool km1 = Msb[ni * 8 + 2 * tig + 1] != 0;
            sf[ni][0] = (qm0 | km0) ? -FLT_MAX : sf[ni][0] + bv0[ni].x;
            sf[ni][1] = (qm0 | km1) ? -FLT_MAX : sf[ni][1] + bv0[ni].y;
            sf[ni][2] = (qm1 | km0) ? -FLT_MAX : sf[ni][2] + bv1[ni].x;
            sf[ni][3] = (qm1 | km1) ? -FLT_MAX : sf[ni][3] + bv1[ni].y;
            mloc0 = fmaxf(mloc0, fmaxf(sf[ni][0], sf[ni][1]));
            mloc1 = fmaxf(mloc1, fmaxf(sf[ni][2], sf[ni][3]));
        }
        mloc0 = fmaxf(mloc0, __shfl_xor_sync(0xffffffffu, mloc0, 1));
        mloc0 = fmaxf(mloc0, __shfl_xor_sync(0xffffffffu, mloc0, 2));
        mloc1 = fmaxf(mloc1, __shfl_xor_sync(0xffffffffu, mloc1, 1));
        mloc1 = fmaxf(mloc1, __shfl_xor_sync(0xffffffffu, mloc1, 2));

        float nm0 = fmaxf(m0, mloc0), nm1 = fmaxf(m1, mloc1);
        float a0 = fast_exp(m0 - nm0), a1 = fast_exp(m1 - nm1);
        m0 = nm0; m1 = nm1;

        float rs0 = 0.f, rs1 = 0.f;
#pragma unroll
        for (int ni = 0; ni < 8; ni++) {
            float p0 = fast_exp(sf[ni][0] - nm0);
            float p1 = fast_exp(sf[ni][1] - nm0);
            float p2 = fast_exp(sf[ni][2] - nm1);
            float p3 = fast_exp(sf[ni][3] - nm1);
            rs0 += p0 + p1; rs1 += p2 + p3;
            *(__half2*)(prow0 + ni * 8 + 2 * tig) = __floats2half2_rn(p0, p1);
            *(__half2*)(prow1 + ni * 8 + 2 * tig) = __floats2half2_rn(p2, p3);
        }
        rs0 += __shfl_xor_sync(0xffffffffu, rs0, 1);
        rs0 += __shfl_xor_sync(0xffffffffu, rs0, 2);
        rs1 += __shfl_xor_sync(0xffffffffu, rs1, 1);
        rs1 += __shfl_xor_sync(0xffffffffu, rs1, 2);
        l0 = l0 * a0 + rs0;
        l1 = l1 * a1 + rs1;
#pragma unroll
        for (int df = 0; df < 8; df++) {
            of[df][0] *= a0; of[df][1] *= a0;
            of[df][2] *= a1; of[df][3] *= a1;
        }
        __syncwarp();

        // O += P @ V  (V tile is [d][key])
#pragma unroll
        for (int kk = 0; kk < 4; kk++) {
            uint32_t af[4];
            af[0] = *(const uint32_t*)(prow0 + kk * 16 + 2 * tig);
            af[1] = *(const uint32_t*)(prow1 + kk * 16 + 2 * tig);
            af[2] = *(const uint32_t*)(prow0 + kk * 16 + 2 * tig + 8);
            af[3] = *(const uint32_t*)(prow1 + kk * 16 + 2 * tig + 8);
#pragma unroll
            for (int df = 0; df < 8; df++) {
                uint32_t bfr[2];
                bfr[0] = *(const uint32_t*)&Vtb[(df * 8 + gid) * VT_H + kk * 16 + 2 * tig];
                bfr[1] = *(const uint32_t*)&Vtb[(df * 8 + gid) * VT_H + kk * 16 + 2 * tig + 8];
                mma16(of[df], af, bfr);
            }
        }
    }

    float inv0 = 1.f / l0, inv1 = 1.f / l1;
    __half* op0 = g_att + ((size_t)(b * N_ + qrow))     * HD_ + h * D_;
    __half* op1 = g_att + ((size_t)(b * N_ + qrow + 8)) * HD_ + h * D_;
#pragma unroll
    for (int df = 0; df < 8; df++) {
        *(__half2*)(op0 + df * 8 + 2 * tig) =
            __floats2half2_rn(of[df][0] * inv0, of[df][1] * inv0);
        *(__half2*)(op1 + df * 8 + 2 * tig) =
            __floats2half2_rn(of[df][2] * inv1, of[df][3] * inv1);
    }
}

// ---------------------------------------------------------------------------
// Launch
// ---------------------------------------------------------------------------
extern "C" void kernel_launch(void* const* d_in, const int* in_sizes, int n_in,
                              void* d_out, int out_size) {
    const float*         x        = (const float*)d_in[0];
    const float*         pos_bias = (const float*)d_in[1];
    const float*         Wqkv     = (const float*)d_in[2];
    const float*         Wout     = (const float*)d_in[3];
    const unsigned char* mask     = (const unsigned char*)d_in[4];
    float*               out      = (float*)d_out;

    __half *xh, *wqkvt, *woutt, *att;
    cudaGetSymbolAddress((void**)&xh,    g_xh);
    cudaGetSymbolAddress((void**)&wqkvt, g_wqkvt);
    cudaGetSymbolAddress((void**)&woutt, g_woutt);
    cudaGetSymbolAddress((void**)&att,   g_att);

    conv_half<<<1024, 256>>>(x, xh, (M_ * C_) / 4);
    transpose_half<<<dim3(QKVC_/32, C_/32), dim3(32, 8)>>>(Wqkv, wqkvt, C_, QKVC_);
    transpose_half<<<dim3(HD_/32,  HD_/32), dim3(32, 8)>>>(Wout, woutt, HD_, HD_);

    gemm_h<QKVC_, true><<<dim3(QKVC_/128, M_/128), 256>>>(xh, wqkvt, nullptr);

    cudaFuncSetAttribute(attn_h, cudaFuncAttributeMaxDynamicSharedMemorySize, ATTN_SMEM_BYTES);
    attn_h<<<dim3(B_, N_/128, H_), 256, ATTN_SMEM_BYTES>>>(pos_bias, mask);

    gemm_h<HD_, false><<<dim3(HD_/128, M_/128), 256>>>(att, woutt, out);
}

// round 8
// speedup vs baseline: 6.2464x; 1.0968x over previous
#include <cuda_runtime.h>
#include <cuda_fp16.h>
#include <math.h>
#include <float.h>
#include <stdint.h>

#define B_    2
#define N_    2048
#define C_    1024
#define H_    16
#define D_    64
#define HD_   1024
#define QKVC_ 3072
#define M_    (B_*N_)
#define SCALE_ 0.125f
#define LOG2E_ 1.4426950408889634f

// Scratch. v stored transposed: [B,H,D,N]. q carries SCALE*LOG2E.
__device__ __half g_q[(size_t)B_*H_*N_*D_];
__device__ __half g_k[(size_t)B_*H_*N_*D_];
__device__ __half g_v[(size_t)B_*H_*D_*N_];
__device__ __half g_att[(size_t)M_*HD_];
__device__ __half g_xh[(size_t)M_*C_];
__device__ __half g_wqkvt[(size_t)QKVC_*C_];
__device__ __half g_woutt[(size_t)HD_*HD_];

// ---------------------------------------------------------------------------
__device__ __forceinline__ void mma16(float c[4], const uint32_t a[4], const uint32_t b[2]) {
    asm volatile("mma.sync.aligned.m16n8k16.row.col.f32.f16.f16.f32 "
        "{%0,%1,%2,%3},{%4,%5,%6,%7},{%8,%9},{%0,%1,%2,%3};"
        : "+f"(c[0]), "+f"(c[1]), "+f"(c[2]), "+f"(c[3])
        : "r"(a[0]), "r"(a[1]), "r"(a[2]), "r"(a[3]), "r"(b[0]), "r"(b[1]));
}
__device__ __forceinline__ uint32_t smem_u32(const void* p) {
    return (uint32_t)__cvta_generic_to_shared(p);
}
__device__ __forceinline__ void cp16(uint32_t dst, const void* src) {
    asm volatile("cp.async.cg.shared.global [%0], [%1], 16;" :: "r"(dst), "l"(src));
}
#define CP_COMMIT() asm volatile("cp.async.commit_group;" ::: "memory")
#define CP_WAIT0()  asm volatile("cp.async.wait_group 0;" ::: "memory")

__device__ __forceinline__ void ldsm_x4(uint32_t r[4], uint32_t addr) {
    asm volatile("ldmatrix.sync.aligned.m8n8.x4.shared.b16 {%0,%1,%2,%3}, [%4];"
        : "=r"(r[0]), "=r"(r[1]), "=r"(r[2]), "=r"(r[3]) : "r"(addr));
}
// 2^x on MUFU
__device__ __forceinline__ float ex2(float x) {
    float y;
    asm("ex2.approx.f32 %0, %1;" : "=f"(y) : "f"(x));
    return y;
}

// ---------------------------------------------------------------------------
// Prep
// ---------------------------------------------------------------------------
__global__ void conv_half(const float* __restrict__ in, __half* __restrict__ out, int n4) {
    int i = blockIdx.x * blockDim.x + threadIdx.x;
    int st = gridDim.x * blockDim.x;
    for (; i < n4; i += st) {
        float4 v = ((const float4*)in)[i];
        ((__half2*)out)[2*i]   = __floats2half2_rn(v.x, v.y);
        ((__half2*)out)[2*i+1] = __floats2half2_rn(v.z, v.w);
    }
}
__global__ void transpose_half(const float* __restrict__ in, __half* __restrict__ out,
                               int K, int N) {
    __shared__ float t[32][33];
    int bx = blockIdx.x * 32, by = blockIdx.y * 32;
    int tx = threadIdx.x, ty = threadIdx.y;
#pragma unroll
    for (int i = 0; i < 4; i++)
        t[ty + i * 8][tx] = in[(size_t)(by + ty + i * 8) * N + bx + tx];
    __syncthreads();
#pragma unroll
    for (int i = 0; i < 4; i++)
        out[(size_t)(bx + ty + i * 8) * K + by + tx] = __float2half_rn(t[tx][ty + i * 8]);
}

// ---------------------------------------------------------------------------
// fp16 TC GEMM with ldmatrix fragments. 128x128 tile, BK=32, 8 warps.
// ---------------------------------------------------------------------------
#define GS 40
#define GT_ELEMS (128*GS)

template<int NC, bool IS_QKV>
__global__ void __launch_bounds__(256, 2) gemm_h(const __half* __restrict__ A,
                                                 const __half* __restrict__ Bt,
                                                 float* __restrict__ out) {
    __shared__ __half As[2][GT_ELEMS];
    __shared__ __half Bs[2][GT_ELEMS];

    const int tid  = threadIdx.x;
    const int lane = tid & 31, warp = tid >> 5;
    const int gid  = lane >> 2, tig = lane & 3;
    const int wm   = warp & 3, wn = warp >> 2;
    const int bm   = blockIdx.y * 128, bn = blockIdx.x * 128;

    const __half* Ab = A  + (size_t)bm * 1024;
    const __half* Bb = Bt + (size_t)bn * 1024;

    auto load_tiles = [&](int s, int k0) {
#pragma unroll
        for (int i = 0; i < 2; i++) {
            int e = tid + i * 256;
            int row = e >> 2, o8 = (e & 3) * 8;
            cp16(smem_u32(&As[s][row * GS + o8]), Ab + (size_t)row * 1024 + k0 + o8);
            cp16(smem_u32(&Bs[s][row * GS + o8]), Bb + (size_t)row * 1024 + k0 + o8);
        }
    };

    // ldmatrix lane offsets
    const int a_lr = lane & 15;              // A row within 16
    const int a_lc = (lane >> 4) << 3;       // A col 0/8
    const int b_lr = lane & 7;               // B row within 8
    const int b_lc = (lane >> 3) << 3;       // B col 0/8/16/24 (covers BK=32)

    float acc[2][8][4];
#pragma unroll
    for (int mi = 0; mi < 2; mi++)
#pragma unroll
        for (int ni = 0; ni < 8; ni++)
#pragma unroll
            for (int q = 0; q < 4; q++) acc[mi][ni][q] = 0.f;

    load_tiles(0, 0);
    CP_COMMIT();

    for (int it = 0; it < 32; it++) {
        CP_WAIT0();
        __syncthreads();
        if (it + 1 < 32) { load_tiles((it + 1) & 1, (it + 1) * 32); CP_COMMIT(); }
        const __half* Asb = As[it & 1];
        const __half* Bsb = Bs[it & 1];

        // A frags: per (mi, kk) one x4
        uint32_t af[2][2][4];
#pragma unroll
        for (int mi = 0; mi < 2; mi++)
#pragma unroll
            for (int kk = 0; kk < 2; kk++)
                ldsm_x4(af[mi][kk], smem_u32(
                    &Asb[(wm * 32 + mi * 16 + a_lr) * GS + kk * 16 + a_lc]));

#pragma unroll
        for (int ni = 0; ni < 8; ni++) {
            uint32_t bf[4];   // [kk0 b0, kk0 b1, kk1 b0, kk1 b1]
            ldsm_x4(bf, smem_u32(&Bsb[(wn * 64 + ni * 8 + b_lr) * GS + b_lc]));
            mma16(acc[0][ni], af[0][0], bf);
            mma16(acc[1][ni], af[1][0], bf);
            mma16(acc[0][ni], af[0][1], bf + 2);
            mma16(acc[1][ni], af[1][1], bf + 2);
        }
        __syncthreads();
    }

    if (IS_QKV) {
#pragma unroll
        for (int mi = 0; mi < 2; mi++)
#pragma unroll
            for (int ni = 0; ni < 8; ni++)
#pragma unroll
                for (int q = 0; q < 4; q++) {
                    int r = bm + wm * 32 + mi * 16 + gid + ((q >= 2) ? 8 : 0);
                    int c = bn + wn * 64 + ni * 8 + 2 * tig + (q & 1);
                    int bb = r >> 11, n = r & 2047;
                    int s  = c % 3,   hd = c / 3;
                    int d  = hd & 63, h = hd >> 6;
                    float val = acc[mi][ni][q];
                    if (s == 0)
                        g_q[((size_t)((bb * H_ + h) * N_ + n)) * D_ + d] =
                            __float2half_rn(val * (SCALE_ * LOG2E_));
                    else if (s == 1)
                        g_k[((size_t)((bb * H_ + h) * N_ + n)) * D_ + d] =
                            __float2half_rn(val);
                    else
                        g_v[((size_t)((bb * H_ + h) * D_ + d)) * N_ + n] =
                            __float2half_rn(val);
                }
    } else {
#pragma unroll
        for (int mi = 0; mi < 2; mi++)
#pragma unroll
            for (int ni = 0; ni < 8; ni++) {
                int r = bm + wm * 32 + mi * 16 + gid;
                int c = bn + wn * 64 + ni * 8 + 2 * tig;
                *(float2*)(out + (size_t)r * NC + c) =
                    make_float2(acc[mi][ni][0], acc[mi][ni][1]);
                *(float2*)(out + (size_t)(r + 8) * NC + c) =
                    make_float2(acc[mi][ni][2], acc[mi][ni][3]);
            }
    }
}

// ---------------------------------------------------------------------------
// Flash attention, fp16 mma + ldmatrix + exp2-domain MUFU softmax.
// ---------------------------------------------------------------------------
#define KS_H 72
#define VT_H 72
#define PS_H 72
#define KS_E (64*KS_H)
#define VT_E (64*VT_H)
#define PS_E (128*PS_H)
#define ATTN_SMEM_BYTES ((2*KS_E + 2*VT_E + PS_E)*2 + 128)

__global__ void __launch_bounds__(256, 2) attn_h(const float* __restrict__ pos_bias,
                                                 const unsigned char* __restrict__ mask) {
    extern __shared__ __half smh[];
    __half* Ks0 = smh;
    __half* Vt0 = smh + 2 * KS_E;
    __half* Ps  = smh + 2 * KS_E + 2 * VT_E;
    unsigned char* Ms0 = (unsigned char*)(Ps + PS_E);

    const int tid = threadIdx.x, lane = tid & 31, wid = tid >> 5;
    const int gid = lane >> 2, tig = lane & 3;
    const int b = blockIdx.x, q0 = blockIdx.y * 128, h = blockIdx.z;
    const int bh = b * H_ + h;

    const __half* qp = g_q + (size_t)bh * N_ * D_;
    const __half* kp = g_k + (size_t)bh * N_ * D_;
    const __half* vp = g_v + (size_t)bh * D_ * N_;
    const unsigned char* maskp = mask + (size_t)b * N_;

    auto loadKV = [&](int s, int kk0) {
        __half* Ksb = Ks0 + s * KS_E;
        __half* Vtb = Vt0 + s * VT_E;
#pragma unroll
        for (int i = 0; i < 2; i++) {
            int e = tid + i * 256;
            int row = e >> 3, o8 = (e & 7) * 8;
            cp16(smem_u32(&Ksb[row * KS_H + o8]), kp + (size_t)(kk0 + row) * D_ + o8);
            cp16(smem_u32(&Vtb[row * VT_H + o8]), vp + (size_t)row * N_ + kk0 + o8);
        }
        if (tid < 4)
            cp16(smem_u32(Ms0 + s * 64 + tid * 16), maskp + kk0 + tid * 16);
    };

    const int qrow = q0 + wid * 16 + gid;
    const __half* qh0 = qp + (size_t)qrow * D_;
    const __half* qh1 = qh0 + 8 * D_;

    uint32_t qf[4][4];
#pragma unroll
    for (int kd = 0; kd < 4; kd++) {
        qf[kd][0] = *(const uint32_t*)(qh0 + kd * 16 + 2 * tig);
        qf[kd][1] = *(const uint32_t*)(qh1 + kd * 16 + 2 * tig);
        qf[kd][2] = *(const uint32_t*)(qh0 + kd * 16 + 2 * tig + 8);
        qf[kd][3] = *(const uint32_t*)(qh1 + kd * 16 + 2 * tig + 8);
    }
    const bool qm0 = maskp[qrow] != 0, qm1 = maskp[qrow + 8] != 0;

    // m/l tracked in log2 domain; p values identical to e-domain softmax.
    float m0 = -FLT_MAX, m1 = -FLT_MAX, l0 = 0.f, l1 = 0.f;
    float of[8][4];
#pragma unroll
    for (int df = 0; df < 8; df++)
#pragma unroll
        for (int q = 0; q < 4; q++) of[df][q] = 0.f;

    const float* bias0 = pos_bias + ((size_t)h * N_ + qrow) * N_;
    const float* bias1 = bias0 + 8 * (size_t)N_;
    __half* prow0 = Ps + (wid * 16 + gid) * PS_H;
    __half* prow1 = prow0 + 8 * PS_H;

    // ldmatrix lane offsets
    const int a_lr = lane & 15, a_lc = (lane >> 4) << 3;
    const int b_lr = lane & 7,  b_lc = (lane >> 3) << 3;

    loadKV(0, 0);
    CP_COMMIT();

    for (int kt = 0; kt < N_ / 64; kt++) {
        const int kk0 = kt * 64;
        CP_WAIT0();
        __syncthreads();
        if (kt + 1 < N_ / 64) { loadKV((kt + 1) & 1, kk0 + 64); CP_COMMIT(); }
        const __half* Ksb = Ks0 + (kt & 1) * KS_E;
        const __half* Vtb = Vt0 + (kt & 1) * VT_E;
        const unsigned char* Msb = Ms0 + (kt & 1) * 64;

        // bias prefetch
        float2 bv0[8], bv1[8];
#pragma unroll
        for (int ni = 0; ni < 8; ni++) {
            bv0[ni] = *(const float2*)(bias0 + kk0 + ni * 8 + 2 * tig);
            bv1[ni] = *(const float2*)(bias1 + kk0 + ni * 8 + 2 * tig);
        }

        // S = Q @ K^T  (ldmatrix x4 covers 2 kd steps per load)
        float sf[8][4];
#pragma unroll
        for (int ni = 0; ni < 8; ni++)
#pragma unroll
            for (int q = 0; q < 4; q++) sf[ni][q] = 0.f;
#pragma unroll
        for (int p = 0; p < 2; p++) {
#pragma unroll
            for (int ni = 0; ni < 8; ni++) {
                uint32_t bq[4];
                ldsm_x4(bq, smem_u32(&Ksb[(ni * 8 + b_lr) * KS_H + p * 32 + b_lc]));
                mma16(sf[ni], qf[2 * p],     bq);
                mma16(sf[ni], qf[2 * p + 1], bq + 2);
            }
        }

        // bias (x LOG2E via FMA) + mask; row max
        float mloc0 = -FLT_MAX, mloc1 = -FLT_MAX;
#pragma unroll
        for (int ni = 0; ni < 8; ni++) {
            bool km0 = Msb[ni * 8 + 2 * tig] != 0;
            bool km1 = Msb[ni * 8 + 2 * tig + 1] != 0;
            sf[ni][0] = (qm0 | km0) ? -FLT_MAX : fmaf(bv0[ni].x, LOG2E_, sf[ni][0]);
            sf[ni][1] = (qm0 | km1) ? -FLT_MAX : fmaf(bv0[ni].y, LOG2E_, sf[ni][1]);
            sf[ni][2] = (qm1 | km0) ? -FLT_MAX : fmaf(bv1[ni].x, LOG2E_, sf[ni][2]);
            sf[ni][3] = (qm1 | km1) ? -FLT_MAX : fmaf(bv1[ni].y, LOG2E_, sf[ni][3]);
            mloc0 = fmaxf(mloc0, fmaxf(sf[ni][0], sf[ni][1]));
            mloc1 = fmaxf(mloc1, fmaxf(sf[ni][2], sf[ni][3]));
        }
        mloc0 = fmaxf(mloc0, __shfl_xor_sync(0xffffffffu, mloc0, 1));
        mloc0 = fmaxf(mloc0, __shfl_xor_sync(0xffffffffu, mloc0, 2));
        mloc1 = fmaxf(mloc1, __shfl_xor_sync(0xffffffffu, mloc1, 1));
        mloc1 = fmaxf(mloc1, __shfl_xor_sync(0xffffffffu, mloc1, 2));

        float nm0 = fmaxf(m0, mloc0), nm1 = fmaxf(m1, mloc1);
        float a0 = ex2(m0 - nm0), a1 = ex2(m1 - nm1);
        m0 = nm0; m1 = nm1;

        float rs0 = 0.f, rs1 = 0.f;
#pragma unroll
        for (int ni = 0; ni < 8; ni++) {
            float p0 = ex2(sf[ni][0] - nm0);
            float p1 = ex2(sf[ni][1] - nm0);
            float p2 = ex2(sf[ni][2] - nm1);
            float p3 = ex2(sf[ni][3] - nm1);
            rs0 += p0 + p1; rs1 += p2 + p3;
            *(__half2*)(prow0 + ni * 8 + 2 * tig) = __floats2half2_rn(p0, p1);
            *(__half2*)(prow1 + ni * 8 + 2 * tig) = __floats2half2_rn(p2, p3);
        }
        rs0 += __shfl_xor_sync(0xffffffffu, rs0, 1);
        rs0 += __shfl_xor_sync(0xffffffffu, rs0, 2);
        rs1 += __shfl_xor_sync(0xffffffffu, rs1, 1);
        rs1 += __shfl_xor_sync(0xffffffffu, rs1, 2);
        l0 = l0 * a0 + rs0;
        l1 = l1 * a1 + rs1;
#pragma unroll
        for (int df = 0; df < 8; df++) {
            of[df][0] *= a0; of[df][1] *= a0;
            of[df][2] *= a1; of[df][3] *= a1;
        }
        __syncwarp();

        // O += P @ V (ldmatrix for P A-frags and V B-frags)
#pragma unroll
        for (int p = 0; p < 2; p++) {
            uint32_t afp[2][4];
            ldsm_x4(afp[0], smem_u32(&Ps[(wid * 16 + a_lr) * PS_H + (2*p)   * 16 + a_lc]));
            ldsm_x4(afp[1], smem_u32(&Ps[(wid * 16 + a_lr) * PS_H + (2*p+1) * 16 + a_lc]));
#pragma unroll
            for (int df = 0; df < 8; df++) {
                uint32_t bq[4];
                ldsm_x4(bq, smem_u32(&Vtb[(df * 8 + b_lr) * VT_H + p * 32 + b_lc]));
                mma16(of[df], afp[0], bq);
                mma16(of[df], afp[1], bq + 2);
            }
        }
    }

    float inv0 = 1.f / l0, inv1 = 1.f / l1;
    __half* op0 = g_att + ((size_t)(b * N_ + qrow))     * HD_ + h * D_;
    __half* op1 = g_att + ((size_t)(b * N_ + qrow + 8)) * HD_ + h * D_;
#pragma unroll
    for (int df = 0; df < 8; df++) {
        *(__half2*)(op0 + df * 8 + 2 * tig) =
            __floats2half2_rn(of[df][0] * inv0, of[df][1] * inv0);
        *(__half2*)(op1 + df * 8 + 2 * tig) =
            __floats2half2_rn(of[df][2] * inv1, of[df][3] * inv1);
    }
}

// ---------------------------------------------------------------------------
extern "C" void kernel_launch(void* const* d_in, const int* in_sizes, int n_in,
                              void* d_out, int out_size) {
    const float*         x        = (const float*)d_in[0];
    const float*         pos_bias = (const float*)d_in[1];
    const float*         Wqkv     = (const float*)d_in[2];
    const float*         Wout     = (const float*)d_in[3];
    const unsigned char* mask     = (const unsigned char*)d_in[4];
    float*               out      = (float*)d_out;

    __half *xh, *wqkvt, *woutt, *att;
    cudaGetSymbolAddress((void**)&xh,    g_xh);
    cudaGetSymbolAddress((void**)&wqkvt, g_wqkvt);
    cudaGetSymbolAddress((void**)&woutt, g_woutt);
    cudaGetSymbolAddress((void**)&att,   g_att);

    conv_half<<<1024, 256>>>(x, xh, (M_ * C_) / 4);
    transpose_half<<<dim3(QKVC_/32, C_/32), dim3(32, 8)>>>(Wqkv, wqkvt, C_, QKVC_);
    transpose_half<<<dim3(HD_/32,  HD_/32), dim3(32, 8)>>>(Wout, woutt, HD_, HD_);

    gemm_h<QKVC_, true><<<dim3(QKVC_/128, M_/128), 256>>>(xh, wqkvt, nullptr);

    cudaFuncSetAttribute(attn_h, cudaFuncAttributeMaxDynamicSharedMemorySize, ATTN_SMEM_BYTES);
    attn_h<<<dim3(B_, N_/128, H_), 256, ATTN_SMEM_BYTES>>>(pos_bias, mask);

    gemm_h<HD_, false><<<dim3(HD_/128, M_/128), 256>>>(att, woutt, out);
}

// round 9
// speedup vs baseline: 6.8791x; 1.1013x over previous
#include <cuda_runtime.h>
#include <cuda_fp16.h>
#include <math.h>
#include <float.h>
#include <stdint.h>

#define B_    2
#define N_    2048
#define C_    1024
#define H_    16
#define D_    64
#define HD_   1024
#define QKVC_ 3072
#define M_    (B_*N_)
#define SCALE_ 0.125f
#define LOG2E_ 1.4426950408889634f

// Scratch. v stored transposed [B,H,D,N]. q carries SCALE*LOG2E.
__device__ __half g_q[(size_t)B_*H_*N_*D_];
__device__ __half g_k[(size_t)B_*H_*N_*D_];
__device__ __half g_v[(size_t)B_*H_*D_*N_];
__device__ __half g_att[(size_t)M_*HD_];
__device__ __half g_xh[(size_t)M_*C_];
__device__ __half g_wqkvt[(size_t)QKVC_*C_];
__device__ __half g_woutt[(size_t)HD_*HD_];
__device__ __half g_qkvh[(size_t)M_*QKVC_];   // flat QKV GEMM output

// ---------------------------------------------------------------------------
__device__ __forceinline__ void mma16(float c[4], const uint32_t a[4], const uint32_t b[2]) {
    asm volatile("mma.sync.aligned.m16n8k16.row.col.f32.f16.f16.f32 "
        "{%0,%1,%2,%3},{%4,%5,%6,%7},{%8,%9},{%0,%1,%2,%3};"
        : "+f"(c[0]), "+f"(c[1]), "+f"(c[2]), "+f"(c[3])
        : "r"(a[0]), "r"(a[1]), "r"(a[2]), "r"(a[3]), "r"(b[0]), "r"(b[1]));
}
__device__ __forceinline__ uint32_t smem_u32(const void* p) {
    return (uint32_t)__cvta_generic_to_shared(p);
}
__device__ __forceinline__ void cp16(uint32_t dst, const void* src) {
    asm volatile("cp.async.cg.shared.global [%0], [%1], 16;" :: "r"(dst), "l"(src));
}
#define CP_COMMIT() asm volatile("cp.async.commit_group;" ::: "memory")
#define CP_WAIT1()  asm volatile("cp.async.wait_group 1;" ::: "memory")
#define CP_WAIT2()  asm volatile("cp.async.wait_group 2;" ::: "memory")

__device__ __forceinline__ void ldsm_x4(uint32_t r[4], uint32_t addr) {
    asm volatile("ldmatrix.sync.aligned.m8n8.x4.shared.b16 {%0,%1,%2,%3}, [%4];"
        : "=r"(r[0]), "=r"(r[1]), "=r"(r[2]), "=r"(r[3]) : "r"(addr));
}
__device__ __forceinline__ float ex2(float x) {
    float y;
    asm("ex2.approx.f32 %0, %1;" : "=f"(y) : "f"(x));
    return y;
}

// ---------------------------------------------------------------------------
// Prep
// ---------------------------------------------------------------------------
__global__ void conv_half(const float* __restrict__ in, __half* __restrict__ out, int n4) {
    int i = blockIdx.x * blockDim.x + threadIdx.x;
    int st = gridDim.x * blockDim.x;
    for (; i < n4; i += st) {
        float4 v = ((const float4*)in)[i];
        ((__half2*)out)[2*i]   = __floats2half2_rn(v.x, v.y);
        ((__half2*)out)[2*i+1] = __floats2half2_rn(v.z, v.w);
    }
}
__global__ void transpose_half(const float* __restrict__ in, __half* __restrict__ out,
                               int K, int N) {
    __shared__ float t[32][33];
    int bx = blockIdx.x * 32, by = blockIdx.y * 32;
    int tx = threadIdx.x, ty = threadIdx.y;
#pragma unroll
    for (int i = 0; i < 4; i++)
        t[ty + i * 8][tx] = in[(size_t)(by + ty + i * 8) * N + bx + tx];
    __syncthreads();
#pragma unroll
    for (int i = 0; i < 4; i++)
        out[(size_t)(bx + ty + i * 8) * K + by + tx] = __float2half_rn(t[tx][ty + i * 8]);
}

// ---------------------------------------------------------------------------
// fp16 TC GEMM, 4-stage cp.async ring (prefetch distance 3), ldmatrix frags.
// 128x128 tile, BK=32, 8 warps. FLAT_HALF: write half output; else float.
// ---------------------------------------------------------------------------
#define GS 40
#define STG_E (128*GS)                 // halves per A (or B) stage
#define GEMM_SMEM (8*STG_E*2)          // 4 stages x (A+B) = 80 KB

template<int NC, bool FLAT_HALF>
__global__ void __launch_bounds__(256, 2) gemm_h(const __half* __restrict__ A,
                                                 const __half* __restrict__ Bt,
                                                 void* __restrict__ outp) {
    extern __shared__ __half smg[];
    __half* As0 = smg;
    __half* Bs0 = smg + 4 * STG_E;

    const int tid  = threadIdx.x;
    const int lane = tid & 31, warp = tid >> 5;
    const int gid  = lane >> 2, tig = lane & 3;
    const int wm   = warp & 3, wn = warp >> 2;
    const int bm   = blockIdx.y * 128, bn = blockIdx.x * 128;

    const __half* Ab = A  + (size_t)bm * 1024;
    const __half* Bb = Bt + (size_t)bn * 1024;

    auto load_tiles = [&](int kt) {
        int s = kt & 3;
        __half* As = As0 + s * STG_E;
        __half* Bs = Bs0 + s * STG_E;
        int k0 = kt * 32;
#pragma unroll
        for (int i = 0; i < 2; i++) {
            int e = tid + i * 256;
            int row = e >> 2, o8 = (e & 3) * 8;
            cp16(smem_u32(&As[row * GS + o8]), Ab + (size_t)row * 1024 + k0 + o8);
            cp16(smem_u32(&Bs[row * GS + o8]), Bb + (size_t)row * 1024 + k0 + o8);
        }
    };

    const int a_lr = lane & 15, a_lc = (lane >> 4) << 3;
    const int b_lr = lane & 7,  b_lc = (lane >> 3) << 3;

    float acc[2][8][4];
#pragma unroll
    for (int mi = 0; mi < 2; mi++)
#pragma unroll
        for (int ni = 0; ni < 8; ni++)
#pragma unroll
            for (int q = 0; q < 4; q++) acc[mi][ni][q] = 0.f;

    load_tiles(0); CP_COMMIT();
    load_tiles(1); CP_COMMIT();
    load_tiles(2); CP_COMMIT();

    for (int it = 0; it < 32; it++) {
        CP_WAIT2();                 // tile it resident
        __syncthreads();            // all warps past compute(it-1); stage (it-1)&3 free
        if (it + 3 < 32) load_tiles(it + 3);
        CP_COMMIT();                // uniform group accounting

        const __half* Asb = As0 + (it & 3) * STG_E;
        const __half* Bsb = Bs0 + (it & 3) * STG_E;

        uint32_t af[2][2][4];
#pragma unroll
        for (int mi = 0; mi < 2; mi++)
#pragma unroll
            for (int kk = 0; kk < 2; kk++)
                ldsm_x4(af[mi][kk], smem_u32(
                    &Asb[(wm * 32 + mi * 16 + a_lr) * GS + kk * 16 + a_lc]));

#pragma unroll
        for (int ni = 0; ni < 8; ni++) {
            uint32_t bf[4];
            ldsm_x4(bf, smem_u32(&Bsb[(wn * 64 + ni * 8 + b_lr) * GS + b_lc]));
            mma16(acc[0][ni], af[0][0], bf);
            mma16(acc[1][ni], af[1][0], bf);
            mma16(acc[0][ni], af[0][1], bf + 2);
            mma16(acc[1][ni], af[1][1], bf + 2);
        }
    }

    if (FLAT_HALF) {
        __half* out = (__half*)outp;
#pragma unroll
        for (int mi = 0; mi < 2; mi++)
#pragma unroll
            for (int ni = 0; ni < 8; ni++) {
                int r = bm + wm * 32 + mi * 16 + gid;
                int c = bn + wn * 64 + ni * 8 + 2 * tig;
                *(__half2*)(out + (size_t)r * NC + c) =
                    __floats2half2_rn(acc[mi][ni][0], acc[mi][ni][1]);
                *(__half2*)(out + (size_t)(r + 8) * NC + c) =
                    __floats2half2_rn(acc[mi][ni][2], acc[mi][ni][3]);
            }
    } else {
        float* out = (float*)outp;
#pragma unroll
        for (int mi = 0; mi < 2; mi++)
#pragma unroll
            for (int ni = 0; ni < 8; ni++) {
                int r = bm + wm * 32 + mi * 16 + gid;
                int c = bn + wn * 64 + ni * 8 + 2 * tig;
                *(float2*)(out + (size_t)r * NC + c) =
                    make_float2(acc[mi][ni][0], acc[mi][ni][1]);
                *(float2*)(out + (size_t)(r + 8) * NC + c) =
                    make_float2(acc[mi][ni][2], acc[mi][ni][3]);
            }
    }
}

// ---------------------------------------------------------------------------
// Scatter: g_qkvh [M][3072] -> g_q/g_k [B,H,N,D] and g_v [B,H,D,N].
// Block = (head h, 64 rows). smem-staged, coalesced half2 stores.
// ---------------------------------------------------------------------------
__global__ void __launch_bounds__(256) scatter_qkv() {
    __shared__ __half t[64 * 192];
    const int h = blockIdx.x, r0 = blockIdx.y * 64, tid = threadIdx.x;
    const __half* src = g_qkvh + (size_t)r0 * QKVC_ + h * 192;

#pragma unroll
    for (int i = 0; i < 6; i++) {
        int e = tid + i * 256;                 // 0..1535 8-half chunks
        int row = e / 24, c8 = e % 24;
        *(float4*)&t[row * 192 + c8 * 8] =
            *(const float4*)(src + (size_t)row * QKVC_ + c8 * 8);
    }
    __syncthreads();

    const int bb = r0 >> 11;                   // batch
    const int nbase = r0 & (N_ - 1);

    // q (s=0, scaled) and k (s=1): 2 x 64 rows x 32 d-pairs
#pragma unroll
    for (int i = 0; i < 16; i++) {
        int e = tid + i * 256;                 // 0..4095
        int s = e >> 11;
        int rem = e & 2047;
        int row = rem >> 5, d = (rem & 31) * 2;
        float v0 = __half2float(t[row * 192 + d * 3 + s]);
        float v1 = __half2float(t[row * 192 + (d + 1) * 3 + s]);
        size_t base = ((size_t)((bb * H_ + h) * N_ + nbase + row)) * D_ + d;
        if (s == 0)
            *(__half2*)(g_q + base) =
                __floats2half2_rn(v0 * (SCALE_ * LOG2E_), v1 * (SCALE_ * LOG2E_));
        else
            *(__half2*)(g_k + base) = __floats2half2_rn(v0, v1);
    }

    // v (s=2), transposed: 64 d x 32 n-pairs
#pragma unroll
    for (int i = 0; i < 8; i++) {
        int e = tid + i * 256;                 // 0..2047
        int d = e >> 5, n = (e & 31) * 2;
        __half v0 = t[n * 192 + d * 3 + 2];
        __half v1 = t[(n + 1) * 192 + d * 3 + 2];
        size_t base = ((size_t)((bb * H_ + h) * D_ + d)) * N_ + nbase + n;
        *(__half2*)(g_v + base) = __halves2half2(v0, v1);
    }
}

// ---------------------------------------------------------------------------
// Flash attention: fp16 mma + ldmatrix + exp2 softmax, 3-stage K/V ring.
// ---------------------------------------------------------------------------
#define KS_H 72
#define VT_H 72
#define PS_H 72
#define KS_E (64*KS_H)
#define VT_E (64*VT_H)
#define PS_E (128*PS_H)
#define ATTN_SMEM_BYTES ((3*KS_E + 3*VT_E + PS_E)*2 + 256)

__global__ void __launch_bounds__(256, 2) attn_h(const float* __restrict__ pos_bias,
                                                 const unsigned char* __restrict__ mask) {
    extern __shared__ __half smh[];
    __half* Ks0 = smh;                          // 3 stages
    __half* Vt0 = smh + 3 * KS_E;               // 3 stages
    __half* Ps  = smh + 3 * KS_E + 3 * VT_E;
    unsigned char* Ms0 = (unsigned char*)(Ps + PS_E);   // 3 x 64

    const int tid = threadIdx.x, lane = tid & 31, wid = tid >> 5;
    const int gid = lane >> 2, tig = lane & 3;
    const int b = blockIdx.x, q0 = blockIdx.y * 128, h = blockIdx.z;
    const int bh = b * H_ + h;

    const __half* qp = g_q + (size_t)bh * N_ * D_;
    const __half* kp = g_k + (size_t)bh * N_ * D_;
    const __half* vp = g_v + (size_t)bh * D_ * N_;
    const unsigned char* maskp = mask + (size_t)b * N_;

    auto loadKV = [&](int kt) {
        int s = kt % 3;
        int kk0 = kt * 64;
        __half* Ksb = Ks0 + s * KS_E;
        __half* Vtb = Vt0 + s * VT_E;
#pragma unroll
        for (int i = 0; i < 2; i++) {
            int e = tid + i * 256;
            int row = e >> 3, o8 = (e & 7) * 8;
            cp16(smem_u32(&Ksb[row * KS_H + o8]), kp + (size_t)(kk0 + row) * D_ + o8);
            cp16(smem_u32(&Vtb[row * VT_H + o8]), vp + (size_t)row * N_ + kk0 + o8);
        }
        if (tid < 4)
            cp16(smem_u32(Ms0 + s * 64 + tid * 16), maskp + kk0 + tid * 16);
    };

    const int qrow = q0 + wid * 16 + gid;
    const __half* qh0 = qp + (size_t)qrow * D_;
    const __half* qh1 = qh0 + 8 * D_;

    uint32_t qf[4][4];
#pragma unroll
    for (int kd = 0; kd < 4; kd++) {
        qf[kd][0] = *(const uint32_t*)(qh0 + kd * 16 + 2 * tig);
        qf[kd][1] = *(const uint32_t*)(qh1 + kd * 16 + 2 * tig);
        qf[kd][2] = *(const uint32_t*)(qh0 + kd * 16 + 2 * tig + 8);
        qf[kd][3] = *(const uint32_t*)(qh1 + kd * 16 + 2 * tig + 8);
    }
    const bool qm0 = maskp[qrow] != 0, qm1 = maskp[qrow + 8] != 0;

    float m0 = -FLT_MAX, m1 = -FLT_MAX, l0 = 0.f, l1 = 0.f;
    float of[8][4];
#pragma unroll
    for (int df = 0; df < 8; df++)
#pragma unroll
        for (int q = 0; q < 4; q++) of[df][q] = 0.f;

    const float* bias0 = pos_bias + ((size_t)h * N_ + qrow) * N_;
    const float* bias1 = bias0 + 8 * (size_t)N_;
    __half* prow0 = Ps + (wid * 16 + gid) * PS_H;
    __half* prow1 = prow0 + 8 * PS_H;

    const int a_lr = lane & 15, a_lc = (lane >> 4) << 3;
    const int b_lr = lane & 7,  b_lc = (lane >> 3) << 3;

    loadKV(0); CP_COMMIT();
    loadKV(1); CP_COMMIT();

    for (int kt = 0; kt < N_ / 64; kt++) {
        const int kk0 = kt * 64;
        CP_WAIT1();                 // tile kt resident
        __syncthreads();
        if (kt + 2 < N_ / 64) loadKV(kt + 2);
        CP_COMMIT();

        const __half* Ksb = Ks0 + (kt % 3) * KS_E;
        const __half* Vtb = Vt0 + (kt % 3) * VT_E;
        const unsigned char* Msb = Ms0 + (kt % 3) * 64;

        float2 bv0[8], bv1[8];
#pragma unroll
        for (int ni = 0; ni < 8; ni++) {
            bv0[ni] = *(const float2*)(bias0 + kk0 + ni * 8 + 2 * tig);
            bv1[ni] = *(const float2*)(bias1 + kk0 + ni * 8 + 2 * tig);
        }

        float sf[8][4];
#pragma unroll
        for (int ni = 0; ni < 8; ni++)
#pragma unroll
            for (int q = 0; q < 4; q++) sf[ni][q] = 0.f;
#pragma unroll
        for (int p = 0; p < 2; p++) {
#pragma unroll
            for (int ni = 0; ni < 8; ni++) {
                uint32_t bq[4];
                ldsm_x4(bq, smem_u32(&Ksb[(ni * 8 + b_lr) * KS_H + p * 32 + b_lc]));
                mma16(sf[ni], qf[2 * p],     bq);
                mma16(sf[ni], qf[2 * p + 1], bq + 2);
            }
        }

        float mloc0 = -FLT_MAX, mloc1 = -FLT_MAX;
#pragma unroll
        for (int ni = 0; ni < 8; ni++) {
            bool km0 = Msb[ni * 8 + 2 * tig] != 0;
            bool km1 = Msb[ni * 8 + 2 * tig + 1] != 0;
            sf[ni][0] = (qm0 | km0) ? -FLT_MAX : fmaf(bv0[ni].x, LOG2E_, sf[ni][0]);
            sf[ni][1] = (qm0 | km1) ? -FLT_MAX : fmaf(bv0[ni].y, LOG2E_, sf[ni][1]);
            sf[ni][2] = (qm1 | km0) ? -FLT_MAX : fmaf(bv1[ni].x, LOG2E_, sf[ni][2]);
            sf[ni][3] = (qm1 | km1) ? -FLT_MAX : fmaf(bv1[ni].y, LOG2E_, sf[ni][3]);
            mloc0 = fmaxf(mloc0, fmaxf(sf[ni][0], sf[ni][1]));
            mloc1 = fmaxf(mloc1, fmaxf(sf[ni][2], sf[ni][3]));
        }
        mloc0 = fmaxf(mloc0, __shfl_xor_sync(0xffffffffu, mloc0, 1));
        mloc0 = fmaxf(mloc0, __shfl_xor_sync(0xffffffffu, mloc0, 2));
        mloc1 = fmaxf(mloc1, __shfl_xor_sync(0xffffffffu, mloc1, 1));
        mloc1 = fmaxf(mloc1, __shfl_xor_sync(0xffffffffu, mloc1, 2));

        float nm0 = fmaxf(m0, mloc0), nm1 = fmaxf(m1, mloc1);
        float a0 = ex2(m0 - nm0), a1 = ex2(m1 - nm1);
        m0 = nm0; m1 = nm1;

        float rs0 = 0.f, rs1 = 0.f;
#pragma unroll
        for (int ni = 0; ni < 8; ni++) {
            float p0 = ex2(sf[ni][0] - nm0);
            float p1 = ex2(sf[ni][1] - nm0);
            float p2 = ex2(sf[ni][2] - nm1);
            float p3 = ex2(sf[ni][3] - nm1);
            rs0 += p0 + p1; rs1 += p2 + p3;
            *(__half2*)(prow0 + ni * 8 + 2 * tig) = __floats2half2_rn(p0, p1);
            *(__half2*)(prow1 + ni * 8 + 2 * tig) = __floats2half2_rn(p2, p3);
        }
        rs0 += __shfl_xor_sync(0xffffffffu, rs0, 1);
        rs0 += __shfl_xor_sync(0xffffffffu, rs0, 2);
        rs1 += __shfl_xor_sync(0xffffffffu, rs1, 1);
        rs1 += __shfl_xor_sync(0xffffffffu, rs1, 2);
        l0 = l0 * a0 + rs0;
        l1 = l1 * a1 + rs1;
#pragma unroll
        for (int df = 0; df < 8; df++) {
            of[df][0] *= a0; of[df][1] *= a0;
            of[df][2] *= a1; of[df][3] *= a1;
        }
        __syncwarp();

#pragma unroll
        for (int p = 0; p < 2; p++) {
            uint32_t afp[2][4];
            ldsm_x4(afp[0], smem_u32(&Ps[(wid * 16 + a_lr) * PS_H + (2*p)   * 16 + a_lc]));
            ldsm_x4(afp[1], smem_u32(&Ps[(wid * 16 + a_lr) * PS_H + (2*p+1) * 16 + a_lc]));
#pragma unroll
            for (int df = 0; df < 8; df++) {
                uint32_t bq[4];
                ldsm_x4(bq, smem_u32(&Vtb[(df * 8 + b_lr) * VT_H + p * 32 + b_lc]));
                mma16(of[df], afp[0], bq);
                mma16(of[df], afp[1], bq + 2);
            }
        }
    }

    float inv0 = 1.f / l0, inv1 = 1.f / l1;
    __half* op0 = g_att + ((size_t)(b * N_ + qrow))     * HD_ + h * D_;
    __half* op1 = g_att + ((size_t)(b * N_ + qrow + 8)) * HD_ + h * D_;
#pragma unroll
    for (int df = 0; df < 8; df++) {
        *(__half2*)(op0 + df * 8 + 2 * tig) =
            __floats2half2_rn(of[df][0] * inv0, of[df][1] * inv0);
        *(__half2*)(op1 + df * 8 + 2 * tig) =
            __floats2half2_rn(of[df][2] * inv1, of[df][3] * inv1);
    }
}

// ---------------------------------------------------------------------------
extern "C" void kernel_launch(void* const* d_in, const int* in_sizes, int n_in,
                              void* d_out, int out_size) {
    const float*         x        = (const float*)d_in[0];
    const float*         pos_bias = (const float*)d_in[1];
    const float*         Wqkv     = (const float*)d_in[2];
    const float*         Wout     = (const float*)d_in[3];
    const unsigned char* mask     = (const unsigned char*)d_in[4];
    float*               out      = (float*)d_out;

    __half *xh, *wqkvt, *woutt, *att, *qkvh;
    cudaGetSymbolAddress((void**)&xh,    g_xh);
    cudaGetSymbolAddress((void**)&wqkvt, g_wqkvt);
    cudaGetSymbolAddress((void**)&woutt, g_woutt);
    cudaGetSymbolAddress((void**)&att,   g_att);
    cudaGetSymbolAddress((void**)&qkvh,  g_qkvh);

    conv_half<<<1024, 256>>>(x, xh, (M_ * C_) / 4);
    transpose_half<<<dim3(QKVC_/32, C_/32), dim3(32, 8)>>>(Wqkv, wqkvt, C_, QKVC_);
    transpose_half<<<dim3(HD_/32,  HD_/32), dim3(32, 8)>>>(Wout, woutt, HD_, HD_);

    cudaFuncSetAttribute(gemm_h<QKVC_, true>,
                         cudaFuncAttributeMaxDynamicSharedMemorySize, GEMM_SMEM);
    gemm_h<QKVC_, true><<<dim3(QKVC_/128, M_/128), 256, GEMM_SMEM>>>(xh, wqkvt, qkvh);

    scatter_qkv<<<dim3(H_, M_/64), 256>>>();

    cudaFuncSetAttribute(attn_h,
                         cudaFuncAttributeMaxDynamicSharedMemorySize, ATTN_SMEM_BYTES);
    attn_h<<<dim3(B_, N_/128, H_), 256, ATTN_SMEM_BYTES>>>(pos_bias, mask);

    cudaFuncSetAttribute(gemm_h<HD_, false>,
                         cudaFuncAttributeMaxDynamicSharedMemorySize, GEMM_SMEM);
    gemm_h<HD_, false><<<dim3(HD_/128, M_/128), 256, GEMM_SMEM>>>(att, woutt, out);
}

// round 10
// speedup vs baseline: 6.9375x; 1.0085x over previous
#include <cuda_runtime.h>
#include <cuda_fp16.h>
#include <math.h>
#include <float.h>
#include <stdint.h>

#define B_    2
#define N_    2048
#define C_    1024
#define H_    16
#define D_    64
#define HD_   1024
#define QKVC_ 3072
#define M_    (B_*N_)
#define SCALE_ 0.125f
#define LOG2E_ 1.4426950408889634f

// Scratch. v stored transposed [B,H,D,N]. q carries SCALE*LOG2E.
__device__ __half g_q[(size_t)B_*H_*N_*D_];
__device__ __half g_k[(size_t)B_*H_*N_*D_];
__device__ __half g_v[(size_t)B_*H_*D_*N_];
__device__ __half g_att[(size_t)M_*HD_];
__device__ __half g_xh[(size_t)M_*C_];
__device__ __half g_wqkvt[(size_t)QKVC_*C_];
__device__ __half g_woutt[(size_t)HD_*HD_];
__device__ __half g_qkvh[(size_t)M_*QKVC_];

// ---------------------------------------------------------------------------
__device__ __forceinline__ void mma16(float c[4], const uint32_t a[4], const uint32_t b[2]) {
    asm volatile("mma.sync.aligned.m16n8k16.row.col.f32.f16.f16.f32 "
        "{%0,%1,%2,%3},{%4,%5,%6,%7},{%8,%9},{%0,%1,%2,%3};"
        : "+f"(c[0]), "+f"(c[1]), "+f"(c[2]), "+f"(c[3])
        : "r"(a[0]), "r"(a[1]), "r"(a[2]), "r"(a[3]), "r"(b[0]), "r"(b[1]));
}
__device__ __forceinline__ uint32_t smem_u32(const void* p) {
    return (uint32_t)__cvta_generic_to_shared(p);
}
__device__ __forceinline__ void cp16(uint32_t dst, const void* src) {
    asm volatile("cp.async.cg.shared.global [%0], [%1], 16;" :: "r"(dst), "l"(src));
}
#define CP_COMMIT() asm volatile("cp.async.commit_group;" ::: "memory")
#define CP_WAIT1()  asm volatile("cp.async.wait_group 1;" ::: "memory")
#define CP_WAIT2()  asm volatile("cp.async.wait_group 2;" ::: "memory")

__device__ __forceinline__ void ldsm_x4(uint32_t r[4], uint32_t addr) {
    asm volatile("ldmatrix.sync.aligned.m8n8.x4.shared.b16 {%0,%1,%2,%3}, [%4];"
        : "=r"(r[0]), "=r"(r[1]), "=r"(r[2]), "=r"(r[3]) : "r"(addr));
}
__device__ __forceinline__ float ex2(float x) {
    float y;
    asm("ex2.approx.f32 %0, %1;" : "=f"(y) : "f"(x));
    return y;
}

// ---------------------------------------------------------------------------
// Prep
// ---------------------------------------------------------------------------
__global__ void conv_half(const float* __restrict__ in, __half* __restrict__ out, int n4) {
    int i = blockIdx.x * blockDim.x + threadIdx.x;
    int st = gridDim.x * blockDim.x;
    for (; i < n4; i += st) {
        float4 v = ((const float4*)in)[i];
        ((__half2*)out)[2*i]   = __floats2half2_rn(v.x, v.y);
        ((__half2*)out)[2*i+1] = __floats2half2_rn(v.z, v.w);
    }
}
__global__ void transpose_half(const float* __restrict__ in, __half* __restrict__ out,
                               int K, int N) {
    __shared__ float t[32][33];
    int bx = blockIdx.x * 32, by = blockIdx.y * 32;
    int tx = threadIdx.x, ty = threadIdx.y;
#pragma unroll
    for (int i = 0; i < 4; i++)
        t[ty + i * 8][tx] = in[(size_t)(by + ty + i * 8) * N + bx + tx];
    __syncthreads();
#pragma unroll
    for (int i = 0; i < 4; i++)
        out[(size_t)(bx + ty + i * 8) * K + by + tx] = __float2half_rn(t[tx][ty + i * 8]);
}

// ---------------------------------------------------------------------------
// fp16 TC GEMM, 4-stage cp.async ring, ldmatrix frags (unchanged from R9).
// ---------------------------------------------------------------------------
#define GS 40
#define STG_E (128*GS)
#define GEMM_SMEM (8*STG_E*2)

template<int NC, bool FLAT_HALF>
__global__ void __launch_bounds__(256, 2) gemm_h(const __half* __restrict__ A,
                                                 const __half* __restrict__ Bt,
                                                 void* __restrict__ outp) {
    extern __shared__ __half smg[];
    __half* As0 = smg;
    __half* Bs0 = smg + 4 * STG_E;

    const int tid  = threadIdx.x;
    const int lane = tid & 31, warp = tid >> 5;
    const int gid  = lane >> 2, tig = lane & 3;
    const int wm   = warp & 3, wn = warp >> 2;
    const int bm   = blockIdx.y * 128, bn = blockIdx.x * 128;

    const __half* Ab = A  + (size_t)bm * 1024;
    const __half* Bb = Bt + (size_t)bn * 1024;

    auto load_tiles = [&](int kt) {
        int s = kt & 3;
        __half* As = As0 + s * STG_E;
        __half* Bs = Bs0 + s * STG_E;
        int k0 = kt * 32;
#pragma unroll
        for (int i = 0; i < 2; i++) {
            int e = tid + i * 256;
            int row = e >> 2, o8 = (e & 3) * 8;
            cp16(smem_u32(&As[row * GS + o8]), Ab + (size_t)row * 1024 + k0 + o8);
            cp16(smem_u32(&Bs[row * GS + o8]), Bb + (size_t)row * 1024 + k0 + o8);
        }
    };

    const int a_lr = lane & 15, a_lc = (lane >> 4) << 3;
    const int b_lr = lane & 7,  b_lc = (lane >> 3) << 3;

    float acc[2][8][4];
#pragma unroll
    for (int mi = 0; mi < 2; mi++)
#pragma unroll
        for (int ni = 0; ni < 8; ni++)
#pragma unroll
            for (int q = 0; q < 4; q++) acc[mi][ni][q] = 0.f;

    load_tiles(0); CP_COMMIT();
    load_tiles(1); CP_COMMIT();
    load_tiles(2); CP_COMMIT();

    for (int it = 0; it < 32; it++) {
        CP_WAIT2();
        __syncthreads();
        if (it + 3 < 32) load_tiles(it + 3);
        CP_COMMIT();

        const __half* Asb = As0 + (it & 3) * STG_E;
        const __half* Bsb = Bs0 + (it & 3) * STG_E;

        uint32_t af[2][2][4];
#pragma unroll
        for (int mi = 0; mi < 2; mi++)
#pragma unroll
            for (int kk = 0; kk < 2; kk++)
                ldsm_x4(af[mi][kk], smem_u32(
                    &Asb[(wm * 32 + mi * 16 + a_lr) * GS + kk * 16 + a_lc]));

#pragma unroll
        for (int ni = 0; ni < 8; ni++) {
            uint32_t bf[4];
            ldsm_x4(bf, smem_u32(&Bsb[(wn * 64 + ni * 8 + b_lr) * GS + b_lc]));
            mma16(acc[0][ni], af[0][0], bf);
            mma16(acc[1][ni], af[1][0], bf);
            mma16(acc[0][ni], af[0][1], bf + 2);
            mma16(acc[1][ni], af[1][1], bf + 2);
        }
    }

    if (FLAT_HALF) {
        __half* out = (__half*)outp;
#pragma unroll
        for (int mi = 0; mi < 2; mi++)
#pragma unroll
            for (int ni = 0; ni < 8; ni++) {
                int r = bm + wm * 32 + mi * 16 + gid;
                int c = bn + wn * 64 + ni * 8 + 2 * tig;
                *(__half2*)(out + (size_t)r * NC + c) =
                    __floats2half2_rn(acc[mi][ni][0], acc[mi][ni][1]);
                *(__half2*)(out + (size_t)(r + 8) * NC + c) =
                    __floats2half2_rn(acc[mi][ni][2], acc[mi][ni][3]);
            }
    } else {
        float* out = (float*)outp;
#pragma unroll
        for (int mi = 0; mi < 2; mi++)
#pragma unroll
            for (int ni = 0; ni < 8; ni++) {
                int r = bm + wm * 32 + mi * 16 + gid;
                int c = bn + wn * 64 + ni * 8 + 2 * tig;
                *(float2*)(out + (size_t)r * NC + c) =
                    make_float2(acc[mi][ni][0], acc[mi][ni][1]);
                *(float2*)(out + (size_t)(r + 8) * NC + c) =
                    make_float2(acc[mi][ni][2], acc[mi][ni][3]);
            }
    }
}

// ---------------------------------------------------------------------------
// Scatter (unchanged from R9)
// ---------------------------------------------------------------------------
__global__ void __launch_bounds__(256) scatter_qkv() {
    __shared__ __half t[64 * 192];
    const int h = blockIdx.x, r0 = blockIdx.y * 64, tid = threadIdx.x;
    const __half* src = g_qkvh + (size_t)r0 * QKVC_ + h * 192;

#pragma unroll
    for (int i = 0; i < 6; i++) {
        int e = tid + i * 256;
        int row = e / 24, c8 = e % 24;
        *(float4*)&t[row * 192 + c8 * 8] =
            *(const float4*)(src + (size_t)row * QKVC_ + c8 * 8);
    }
    __syncthreads();

    const int bb = r0 >> 11;
    const int nbase = r0 & (N_ - 1);

#pragma unroll
    for (int i = 0; i < 16; i++) {
        int e = tid + i * 256;
        int s = e >> 11;
        int rem = e & 2047;
        int row = rem >> 5, d = (rem & 31) * 2;
        float v0 = __half2float(t[row * 192 + d * 3 + s]);
        float v1 = __half2float(t[row * 192 + (d + 1) * 3 + s]);
        size_t base = ((size_t)((bb * H_ + h) * N_ + nbase + row)) * D_ + d;
        if (s == 0)
            *(__half2*)(g_q + base) =
                __floats2half2_rn(v0 * (SCALE_ * LOG2E_), v1 * (SCALE_ * LOG2E_));
        else
            *(__half2*)(g_k + base) = __floats2half2_rn(v0, v1);
    }

#pragma unroll
    for (int i = 0; i < 8; i++) {
        int e = tid + i * 256;
        int d = e >> 5, n = (e & 31) * 2;
        __half v0 = t[n * 192 + d * 3 + 2];
        __half v1 = t[(n + 1) * 192 + d * 3 + 2];
        size_t base = ((size_t)((bb * H_ + h) * D_ + d)) * N_ + nbase + n;
        *(__half2*)(g_v + base) = __halves2half2(v0, v1);
    }
}

// ---------------------------------------------------------------------------
// Flash attention: P stays in registers (S-acc layout == PV A-frag layout),
// mask fast path, alpha-skip. 3-stage K/V ring; no P smem.
// ---------------------------------------------------------------------------
#define KS_H 72
#define VT_H 72
#define KS_E (64*KS_H)
#define VT_E (64*VT_H)
#define ATTN_SMEM_BYTES ((3*KS_E + 3*VT_E)*2 + 256)

__global__ void __launch_bounds__(256, 2) attn_h(const float* __restrict__ pos_bias,
                                                 const unsigned char* __restrict__ mask) {
    extern __shared__ __half smh[];
    __half* Ks0 = smh;
    __half* Vt0 = smh + 3 * KS_E;
    unsigned char* Ms0 = (unsigned char*)(Vt0 + 3 * VT_E);   // 3 x 64

    const int tid = threadIdx.x, lane = tid & 31, wid = tid >> 5;
    const int gid = lane >> 2, tig = lane & 3;
    const int b = blockIdx.x, q0 = blockIdx.y * 128, h = blockIdx.z;
    const int bh = b * H_ + h;

    const __half* qp = g_q + (size_t)bh * N_ * D_;
    const __half* kp = g_k + (size_t)bh * N_ * D_;
    const __half* vp = g_v + (size_t)bh * D_ * N_;
    const unsigned char* maskp = mask + (size_t)b * N_;

    auto loadKV = [&](int kt) {
        int s = kt % 3;
        int kk0 = kt * 64;
        __half* Ksb = Ks0 + s * KS_E;
        __half* Vtb = Vt0 + s * VT_E;
#pragma unroll
        for (int i = 0; i < 2; i++) {
            int e = tid + i * 256;
            int row = e >> 3, o8 = (e & 7) * 8;
            cp16(smem_u32(&Ksb[row * KS_H + o8]), kp + (size_t)(kk0 + row) * D_ + o8);
            cp16(smem_u32(&Vtb[row * VT_H + o8]), vp + (size_t)row * N_ + kk0 + o8);
        }
        if (tid < 4)
            cp16(smem_u32(Ms0 + s * 64 + tid * 16), maskp + kk0 + tid * 16);
    };

    const int qrow = q0 + wid * 16 + gid;
    const __half* qh0 = qp + (size_t)qrow * D_;
    const __half* qh1 = qh0 + 8 * D_;

    uint32_t qf[4][4];
#pragma unroll
    for (int kd = 0; kd < 4; kd++) {
        qf[kd][0] = *(const uint32_t*)(qh0 + kd * 16 + 2 * tig);
        qf[kd][1] = *(const uint32_t*)(qh1 + kd * 16 + 2 * tig);
        qf[kd][2] = *(const uint32_t*)(qh0 + kd * 16 + 2 * tig + 8);
        qf[kd][3] = *(const uint32_t*)(qh1 + kd * 16 + 2 * tig + 8);
    }
    const bool qm0 = maskp[qrow] != 0, qm1 = maskp[qrow + 8] != 0;
    const bool qmask = qm0 | qm1;

    float m0 = -FLT_MAX, m1 = -FLT_MAX, l0 = 0.f, l1 = 0.f;
    float of[8][4];
#pragma unroll
    for (int df = 0; df < 8; df++)
#pragma unroll
        for (int q = 0; q < 4; q++) of[df][q] = 0.f;

    const float* bias0 = pos_bias + ((size_t)h * N_ + qrow) * N_;
    const float* bias1 = bias0 + 8 * (size_t)N_;

    const int b_lr = lane & 7, b_lc = (lane >> 3) << 3;

    loadKV(0); CP_COMMIT();
    loadKV(1); CP_COMMIT();

    for (int kt = 0; kt < N_ / 64; kt++) {
        const int kk0 = kt * 64;
        CP_WAIT1();
        __syncthreads();
        if (kt + 2 < N_ / 64) loadKV(kt + 2);
        CP_COMMIT();

        const __half* Ksb = Ks0 + (kt % 3) * KS_E;
        const __half* Vtb = Vt0 + (kt % 3) * VT_E;
        const unsigned char* Msb = Ms0 + (kt % 3) * 64;

        // bias prefetch
        float2 bv0[8], bv1[8];
#pragma unroll
        for (int ni = 0; ni < 8; ni++) {
            bv0[ni] = *(const float2*)(bias0 + kk0 + ni * 8 + 2 * tig);
            bv1[ni] = *(const float2*)(bias1 + kk0 + ni * 8 + 2 * tig);
        }

        // uniform "any key masked in this tile" flag (broadcast LDS)
        const uint4* mw = (const uint4*)Msb;
        uint4 w0 = mw[0], w1 = mw[1], w2 = mw[2], w3 = mw[3];
        bool tmask = ((w0.x | w0.y | w0.z | w0.w | w1.x | w1.y | w1.z | w1.w |
                       w2.x | w2.y | w2.z | w2.w | w3.x | w3.y | w3.z | w3.w) != 0u)
                     | qmask;

        // S = Q @ K^T
        float sf[8][4];
#pragma unroll
        for (int ni = 0; ni < 8; ni++)
#pragma unroll
            for (int q = 0; q < 4; q++) sf[ni][q] = 0.f;
#pragma unroll
        for (int p = 0; p < 2; p++) {
#pragma unroll
            for (int ni = 0; ni < 8; ni++) {
                uint32_t bq[4];
                ldsm_x4(bq, smem_u32(&Ksb[(ni * 8 + b_lr) * KS_H + p * 32 + b_lc]));
                mma16(sf[ni], qf[2 * p],     bq);
                mma16(sf[ni], qf[2 * p + 1], bq + 2);
            }
        }

        // bias + (rare) mask, row max
        float mloc0 = -FLT_MAX, mloc1 = -FLT_MAX;
        if (!tmask) {
#pragma unroll
            for (int ni = 0; ni < 8; ni++) {
                sf[ni][0] = fmaf(bv0[ni].x, LOG2E_, sf[ni][0]);
                sf[ni][1] = fmaf(bv0[ni].y, LOG2E_, sf[ni][1]);
                sf[ni][2] = fmaf(bv1[ni].x, LOG2E_, sf[ni][2]);
                sf[ni][3] = fmaf(bv1[ni].y, LOG2E_, sf[ni][3]);
                mloc0 = fmaxf(mloc0, fmaxf(sf[ni][0], sf[ni][1]));
                mloc1 = fmaxf(mloc1, fmaxf(sf[ni][2], sf[ni][3]));
            }
        } else {
#pragma unroll
            for (int ni = 0; ni < 8; ni++) {
                bool km0 = Msb[ni * 8 + 2 * tig] != 0;
                bool km1 = Msb[ni * 8 + 2 * tig + 1] != 0;
                sf[ni][0] = (qm0 | km0) ? -FLT_MAX : fmaf(bv0[ni].x, LOG2E_, sf[ni][0]);
                sf[ni][1] = (qm0 | km1) ? -FLT_MAX : fmaf(bv0[ni].y, LOG2E_, sf[ni][1]);
                sf[ni][2] = (qm1 | km0) ? -FLT_MAX : fmaf(bv1[ni].x, LOG2E_, sf[ni][2]);
                sf[ni][3] = (qm1 | km1) ? -FLT_MAX : fmaf(bv1[ni].y, LOG2E_, sf[ni][3]);
                mloc0 = fmaxf(mloc0, fmaxf(sf[ni][0], sf[ni][1]));
                mloc1 = fmaxf(mloc1, fmaxf(sf[ni][2], sf[ni][3]));
            }
        }
        mloc0 = fmaxf(mloc0, __shfl_xor_sync(0xffffffffu, mloc0, 1));
        mloc0 = fmaxf(mloc0, __shfl_xor_sync(0xffffffffu, mloc0, 2));
        mloc1 = fmaxf(mloc1, __shfl_xor_sync(0xffffffffu, mloc1, 1));
        mloc1 = fmaxf(mloc1, __shfl_xor_sync(0xffffffffu, mloc1, 2));

        float nm0 = fmaxf(m0, mloc0), nm1 = fmaxf(m1, mloc1);
        bool rescale = (nm0 != m0) | (nm1 != m1);
        if (rescale) {
            float a0 = ex2(m0 - nm0), a1 = ex2(m1 - nm1);
            l0 *= a0; l1 *= a1;
#pragma unroll
            for (int df = 0; df < 8; df++) {
                of[df][0] *= a0; of[df][1] *= a0;
                of[df][2] *= a1; of[df][3] *= a1;
            }
            m0 = nm0; m1 = nm1;
        }

        // p in registers, PV A-fragment layout
        uint32_t ph[8][2];
        float rs0 = 0.f, rs1 = 0.f;
#pragma unroll
        for (int ni = 0; ni < 8; ni++) {
            float p0 = ex2(sf[ni][0] - m0);
            float p1 = ex2(sf[ni][1] - m0);
            float p2 = ex2(sf[ni][2] - m1);
            float p3 = ex2(sf[ni][3] - m1);
            rs0 += p0 + p1; rs1 += p2 + p3;
            __half2 h01 = __floats2half2_rn(p0, p1);
            __half2 h23 = __floats2half2_rn(p2, p3);
            ph[ni][0] = *(uint32_t*)&h01;
            ph[ni][1] = *(uint32_t*)&h23;
        }
        rs0 += __shfl_xor_sync(0xffffffffu, rs0, 1);
        rs0 += __shfl_xor_sync(0xffffffffu, rs0, 2);
        rs1 += __shfl_xor_sync(0xffffffffu, rs1, 1);
        rs1 += __shfl_xor_sync(0xffffffffu, rs1, 2);
        l0 += rs0;
        l1 += rs1;

        // O += P @ V : A-frags straight from ph registers
#pragma unroll
        for (int p = 0; p < 2; p++) {
            uint32_t af0[4] = { ph[4*p    ][0], ph[4*p    ][1],
                                ph[4*p + 1][0], ph[4*p + 1][1] };
            uint32_t af1[4] = { ph[4*p + 2][0], ph[4*p + 2][1],
                                ph[4*p + 3][0], ph[4*p + 3][1] };
#pragma unroll
            for (int df = 0; df < 8; df++) {
                uint32_t bq[4];
                ldsm_x4(bq, smem_u32(&Vtb[(df * 8 + b_lr) * VT_H + p * 32 + b_lc]));
                mma16(of[df], af0, bq);
                mma16(of[df], af1, bq + 2);
            }
        }
    }

    float inv0 = 1.f / l0, inv1 = 1.f / l1;
    __half* op0 = g_att + ((size_t)(b * N_ + qrow))     * HD_ + h * D_;
    __half* op1 = g_att + ((size_t)(b * N_ + qrow + 8)) * HD_ + h * D_;
#pragma unroll
    for (int df = 0; df < 8; df++) {
        *(__half2*)(op0 + df * 8 + 2 * tig) =
            __floats2half2_rn(of[df][0] * inv0, of[df][1] * inv0);
        *(__half2*)(op1 + df * 8 + 2 * tig) =
            __floats2half2_rn(of[df][2] * inv1, of[df][3] * inv1);
    }
}

// ---------------------------------------------------------------------------
extern "C" void kernel_launch(void* const* d_in, const int* in_sizes, int n_in,
                              void* d_out, int out_size) {
    const float*         x        = (const float*)d_in[0];
    const float*         pos_bias = (const float*)d_in[1];
    const float*         Wqkv     = (const float*)d_in[2];
    const float*         Wout     = (const float*)d_in[3];
    const unsigned char* mask     = (const unsigned char*)d_in[4];
    float*               out      = (float*)d_out;

    __half *xh, *wqkvt, *woutt, *att, *qkvh;
    cudaGetSymbolAddress((void**)&xh,    g_xh);
    cudaGetSymbolAddress((void**)&wqkvt, g_wqkvt);
    cudaGetSymbolAddress((void**)&woutt, g_woutt);
    cudaGetSymbolAddress((void**)&att,   g_att);
    cudaGetSymbolAddress((void**)&qkvh,  g_qkvh);

    conv_half<<<1024, 256>>>(x, xh, (M_ * C_) / 4);
    transpose_half<<<dim3(QKVC_/32, C_/32), dim3(32, 8)>>>(Wqkv, wqkvt, C_, QKVC_);
    transpose_half<<<dim3(HD_/32,  HD_/32), dim3(32, 8)>>>(Wout, woutt, HD_, HD_);

    cudaFuncSetAttribute(gemm_h<QKVC_, true>,
                         cudaFuncAttributeMaxDynamicSharedMemorySize, GEMM_SMEM);
    gemm_h<QKVC_, true><<<dim3(QKVC_/128, M_/128), 256, GEMM_SMEM>>>(xh, wqkvt, qkvh);

    scatter_qkv<<<dim3(H_, M_/64), 256>>>();

    cudaFuncSetAttribute(attn_h,
                         cudaFuncAttributeMaxDynamicSharedMemorySize, ATTN_SMEM_BYTES);
    attn_h<<<dim3(B_, N_/128, H_), 256, ATTN_SMEM_BYTES>>>(pos_bias, mask);

    cudaFuncSetAttribute(gemm_h<HD_, false>,
                         cudaFuncAttributeMaxDynamicSharedMemorySize, GEMM_SMEM);
    gemm_h<HD_, false><<<dim3(HD_/128, M_/128), 256, GEMM_SMEM>>>(att, woutt, out);
}

// round 11
// speedup vs baseline: 7.2071x; 1.0388x over previous
#include <cuda_runtime.h>
#include <cuda_fp16.h>
#include <math.h>
#include <float.h>
#include <stdint.h>

#define B_    2
#define N_    2048
#define C_    1024
#define H_    16
#define D_    64
#define HD_   1024
#define QKVC_ 3072
#define M_    (B_*N_)
#define SCALE_ 0.125f
#define LOG2E_ 1.4426950408889634f

// Scratch. v stored transposed [B,H,D,N]. q carries SCALE*LOG2E.
__device__ __half g_q[(size_t)B_*H_*N_*D_];
__device__ __half g_k[(size_t)B_*H_*N_*D_];
__device__ __half g_v[(size_t)B_*H_*D_*N_];
__device__ __half g_att[(size_t)M_*HD_];
__device__ __half g_xh[(size_t)M_*C_];
__device__ __half g_wqkvt[(size_t)QKVC_*C_];
__device__ __half g_woutt[(size_t)HD_*HD_];
__device__ __half g_qkvh[(size_t)M_*QKVC_];

// ---------------------------------------------------------------------------
__device__ __forceinline__ void mma16(float c[4], const uint32_t a[4], const uint32_t b[2]) {
    asm volatile("mma.sync.aligned.m16n8k16.row.col.f32.f16.f16.f32 "
        "{%0,%1,%2,%3},{%4,%5,%6,%7},{%8,%9},{%0,%1,%2,%3};"
        : "+f"(c[0]), "+f"(c[1]), "+f"(c[2]), "+f"(c[3])
        : "r"(a[0]), "r"(a[1]), "r"(a[2]), "r"(a[3]), "r"(b[0]), "r"(b[1]));
}
__device__ __forceinline__ uint32_t smem_u32(const void* p) {
    return (uint32_t)__cvta_generic_to_shared(p);
}
__device__ __forceinline__ void cp16(uint32_t dst, const void* src) {
    asm volatile("cp.async.cg.shared.global [%0], [%1], 16;" :: "r"(dst), "l"(src));
}
#define CP_COMMIT() asm volatile("cp.async.commit_group;" ::: "memory")
#define CP_WAIT1()  asm volatile("cp.async.wait_group 1;" ::: "memory")
#define CP_WAIT2()  asm volatile("cp.async.wait_group 2;" ::: "memory")

__device__ __forceinline__ void ldsm_x4(uint32_t r[4], uint32_t addr) {
    asm volatile("ldmatrix.sync.aligned.m8n8.x4.shared.b16 {%0,%1,%2,%3}, [%4];"
        : "=r"(r[0]), "=r"(r[1]), "=r"(r[2]), "=r"(r[3]) : "r"(addr));
}
__device__ __forceinline__ float ex2(float x) {
    float y;
    asm("ex2.approx.f32 %0, %1;" : "=f"(y) : "f"(x));
    return y;
}
// pack two fp32 into half2 (lo, hi) then 2^x elementwise on MUFU
__device__ __forceinline__ uint32_t ex2_h2(float lo, float hi) {
    uint32_t x, y;
    asm("cvt.rn.f16x2.f32 %0, %1, %2;" : "=r"(x) : "f"(hi), "f"(lo));
    asm("ex2.approx.f16x2 %0, %1;" : "=r"(y) : "r"(x));
    return y;
}

// ---------------------------------------------------------------------------
// Prep
// ---------------------------------------------------------------------------
__global__ void conv_half(const float* __restrict__ in, __half* __restrict__ out, int n4) {
    int i = blockIdx.x * blockDim.x + threadIdx.x;
    int st = gridDim.x * blockDim.x;
    for (; i < n4; i += st) {
        float4 v = ((const float4*)in)[i];
        ((__half2*)out)[2*i]   = __floats2half2_rn(v.x, v.y);
        ((__half2*)out)[2*i+1] = __floats2half2_rn(v.z, v.w);
    }
}
__global__ void transpose_half(const float* __restrict__ in, __half* __restrict__ out,
                               int K, int N) {
    __shared__ float t[32][33];
    int bx = blockIdx.x * 32, by = blockIdx.y * 32;
    int tx = threadIdx.x, ty = threadIdx.y;
#pragma unroll
    for (int i = 0; i < 4; i++)
        t[ty + i * 8][tx] = in[(size_t)(by + ty + i * 8) * N + bx + tx];
    __syncthreads();
#pragma unroll
    for (int i = 0; i < 4; i++)
        out[(size_t)(bx + ty + i * 8) * K + by + tx] = __float2half_rn(t[tx][ty + i * 8]);
}

// ---------------------------------------------------------------------------
// fp16 TC GEMM, 4-stage cp.async ring, ldmatrix frags (unchanged from R9).
// ---------------------------------------------------------------------------
#define GS 40
#define STG_E (128*GS)
#define GEMM_SMEM (8*STG_E*2)

template<int NC, bool FLAT_HALF>
__global__ void __launch_bounds__(256, 2) gemm_h(const __half* __restrict__ A,
                                                 const __half* __restrict__ Bt,
                                                 void* __restrict__ outp) {
    extern __shared__ __half smg[];
    __half* As0 = smg;
    __half* Bs0 = smg + 4 * STG_E;

    const int tid  = threadIdx.x;
    const int lane = tid & 31, warp = tid >> 5;
    const int gid  = lane >> 2, tig = lane & 3;
    const int wm   = warp & 3, wn = warp >> 2;
    const int bm   = blockIdx.y * 128, bn = blockIdx.x * 128;

    const __half* Ab = A  + (size_t)bm * 1024;
    const __half* Bb = Bt + (size_t)bn * 1024;

    auto load_tiles = [&](int kt) {
        int s = kt & 3;
        __half* As = As0 + s * STG_E;
        __half* Bs = Bs0 + s * STG_E;
        int k0 = kt * 32;
#pragma unroll
        for (int i = 0; i < 2; i++) {
            int e = tid + i * 256;
            int row = e >> 2, o8 = (e & 3) * 8;
            cp16(smem_u32(&As[row * GS + o8]), Ab + (size_t)row * 1024 + k0 + o8);
            cp16(smem_u32(&Bs[row * GS + o8]), Bb + (size_t)row * 1024 + k0 + o8);
        }
    };

    const int a_lr = lane & 15, a_lc = (lane >> 4) << 3;
    const int b_lr = lane & 7,  b_lc = (lane >> 3) << 3;

    float acc[2][8][4];
#pragma unroll
    for (int mi = 0; mi < 2; mi++)
#pragma unroll
        for (int ni = 0; ni < 8; ni++)
#pragma unroll
            for (int q = 0; q < 4; q++) acc[mi][ni][q] = 0.f;

    load_tiles(0); CP_COMMIT();
    load_tiles(1); CP_COMMIT();
    load_tiles(2); CP_COMMIT();

    for (int it = 0; it < 32; it++) {
        CP_WAIT2();
        __syncthreads();
        if (it + 3 < 32) load_tiles(it + 3);
        CP_COMMIT();

        const __half* Asb = As0 + (it & 3) * STG_E;
        const __half* Bsb = Bs0 + (it & 3) * STG_E;

        uint32_t af[2][2][4];
#pragma unroll
        for (int mi = 0; mi < 2; mi++)
#pragma unroll
            for (int kk = 0; kk < 2; kk++)
                ldsm_x4(af[mi][kk], smem_u32(
                    &Asb[(wm * 32 + mi * 16 + a_lr) * GS + kk * 16 + a_lc]));

#pragma unroll
        for (int ni = 0; ni < 8; ni++) {
            uint32_t bf[4];
            ldsm_x4(bf, smem_u32(&Bsb[(wn * 64 + ni * 8 + b_lr) * GS + b_lc]));
            mma16(acc[0][ni], af[0][0], bf);
            mma16(acc[1][ni], af[1][0], bf);
            mma16(acc[0][ni], af[0][1], bf + 2);
            mma16(acc[1][ni], af[1][1], bf + 2);
        }
    }

    if (FLAT_HALF) {
        __half* out = (__half*)outp;
#pragma unroll
        for (int mi = 0; mi < 2; mi++)
#pragma unroll
            for (int ni = 0; ni < 8; ni++) {
                int r = bm + wm * 32 + mi * 16 + gid;
                int c = bn + wn * 64 + ni * 8 + 2 * tig;
                *(__half2*)(out + (size_t)r * NC + c) =
                    __floats2half2_rn(acc[mi][ni][0], acc[mi][ni][1]);
                *(__half2*)(out + (size_t)(r + 8) * NC + c) =
                    __floats2half2_rn(acc[mi][ni][2], acc[mi][ni][3]);
            }
    } else {
        float* out = (float*)outp;
#pragma unroll
        for (int mi = 0; mi < 2; mi++)
#pragma unroll
            for (int ni = 0; ni < 8; ni++) {
                int r = bm + wm * 32 + mi * 16 + gid;
                int c = bn + wn * 64 + ni * 8 + 2 * tig;
                *(float2*)(out + (size_t)r * NC + c) =
                    make_float2(acc[mi][ni][0], acc[mi][ni][1]);
                *(float2*)(out + (size_t)(r + 8) * NC + c) =
                    make_float2(acc[mi][ni][2], acc[mi][ni][3]);
            }
    }
}

// ---------------------------------------------------------------------------
// Scatter (unchanged)
// ---------------------------------------------------------------------------
__global__ void __launch_bounds__(256) scatter_qkv() {
    __shared__ __half t[64 * 192];
    const int h = blockIdx.x, r0 = blockIdx.y * 64, tid = threadIdx.x;
    const __half* src = g_qkvh + (size_t)r0 * QKVC_ + h * 192;

#pragma unroll
    for (int i = 0; i < 6; i++) {
        int e = tid + i * 256;
        int row = e / 24, c8 = e % 24;
        *(float4*)&t[row * 192 + c8 * 8] =
            *(const float4*)(src + (size_t)row * QKVC_ + c8 * 8);
    }
    __syncthreads();

    const int bb = r0 >> 11;
    const int nbase = r0 & (N_ - 1);

#pragma unroll
    for (int i = 0; i < 16; i++) {
        int e = tid + i * 256;
        int s = e >> 11;
        int rem = e & 2047;
        int row = rem >> 5, d = (rem & 31) * 2;
        float v0 = __half2float(t[row * 192 + d * 3 + s]);
        float v1 = __half2float(t[row * 192 + (d + 1) * 3 + s]);
        size_t base = ((size_t)((bb * H_ + h) * N_ + nbase + row)) * D_ + d;
        if (s == 0)
            *(__half2*)(g_q + base) =
                __floats2half2_rn(v0 * (SCALE_ * LOG2E_), v1 * (SCALE_ * LOG2E_));
        else
            *(__half2*)(g_k + base) = __floats2half2_rn(v0, v1);
    }

#pragma unroll
    for (int i = 0; i < 8; i++) {
        int e = tid + i * 256;
        int d = e >> 5, n = (e & 31) * 2;
        __half v0 = t[n * 192 + d * 3 + 2];
        __half v1 = t[(n + 1) * 192 + d * 3 + 2];
        size_t base = ((size_t)((bb * H_ + h) * D_ + d)) * N_ + nbase + n;
        *(__half2*)(g_v + base) = __halves2half2(v0, v1);
    }
}

// ---------------------------------------------------------------------------
// Flash attention: P in registers; ex2.approx.f16x2 softmax (MUFU halved);
// row-sum l via ones-mma into fp32 accumulators (no per-tile shfl sum).
// ---------------------------------------------------------------------------
#define KS_H 72
#define VT_H 72
#define KS_E (64*KS_H)
#define VT_E (64*VT_H)
#define ATTN_SMEM_BYTES ((3*KS_E + 3*VT_E)*2 + 256)
#define ONES2 0x3C003C00u

__global__ void __launch_bounds__(256, 2) attn_h(const float* __restrict__ pos_bias,
                                                 const unsigned char* __restrict__ mask) {
    extern __shared__ __half smh[];
    __half* Ks0 = smh;
    __half* Vt0 = smh + 3 * KS_E;
    unsigned char* Ms0 = (unsigned char*)(Vt0 + 3 * VT_E);

    const int tid = threadIdx.x, lane = tid & 31, wid = tid >> 5;
    const int gid = lane >> 2, tig = lane & 3;
    const int b = blockIdx.x, q0 = blockIdx.y * 128, h = blockIdx.z;
    const int bh = b * H_ + h;

    const __half* qp = g_q + (size_t)bh * N_ * D_;
    const __half* kp = g_k + (size_t)bh * N_ * D_;
    const __half* vp = g_v + (size_t)bh * D_ * N_;
    const unsigned char* maskp = mask + (size_t)b * N_;

    auto loadKV = [&](int kt) {
        int s = kt % 3;
        int kk0 = kt * 64;
        __half* Ksb = Ks0 + s * KS_E;
        __half* Vtb = Vt0 + s * VT_E;
#pragma unroll
        for (int i = 0; i < 2; i++) {
            int e = tid + i * 256;
            int row = e >> 3, o8 = (e & 7) * 8;
            cp16(smem_u32(&Ksb[row * KS_H + o8]), kp + (size_t)(kk0 + row) * D_ + o8);
            cp16(smem_u32(&Vtb[row * VT_H + o8]), vp + (size_t)row * N_ + kk0 + o8);
        }
        if (tid < 4)
            cp16(smem_u32(Ms0 + s * 64 + tid * 16), maskp + kk0 + tid * 16);
    };

    const int qrow = q0 + wid * 16 + gid;
    const __half* qh0 = qp + (size_t)qrow * D_;
    const __half* qh1 = qh0 + 8 * D_;

    uint32_t qf[4][4];
#pragma unroll
    for (int kd = 0; kd < 4; kd++) {
        qf[kd][0] = *(const uint32_t*)(qh0 + kd * 16 + 2 * tig);
        qf[kd][1] = *(const uint32_t*)(qh1 + kd * 16 + 2 * tig);
        qf[kd][2] = *(const uint32_t*)(qh0 + kd * 16 + 2 * tig + 8);
        qf[kd][3] = *(const uint32_t*)(qh1 + kd * 16 + 2 * tig + 8);
    }
    const bool qm0 = maskp[qrow] != 0, qm1 = maskp[qrow + 8] != 0;
    const bool qmask = qm0 | qm1;

    float m0 = -FLT_MAX, m1 = -FLT_MAX;
    float of[8][4];
    float ol[4] = {0.f, 0.f, 0.f, 0.f};     // row sums of P (l0 = ol[0], l1 = ol[2])
#pragma unroll
    for (int df = 0; df < 8; df++)
#pragma unroll
        for (int q = 0; q < 4; q++) of[df][q] = 0.f;

    const float* bias0 = pos_bias + ((size_t)h * N_ + qrow) * N_;
    const float* bias1 = bias0 + 8 * (size_t)N_;

    const int b_lr = lane & 7, b_lc = (lane >> 3) << 3;
    const uint32_t ones[2] = {ONES2, ONES2};

    loadKV(0); CP_COMMIT();
    loadKV(1); CP_COMMIT();

    for (int kt = 0; kt < N_ / 64; kt++) {
        const int kk0 = kt * 64;
        CP_WAIT1();
        __syncthreads();
        if (kt + 2 < N_ / 64) loadKV(kt + 2);
        CP_COMMIT();

        const __half* Ksb = Ks0 + (kt % 3) * KS_E;
        const __half* Vtb = Vt0 + (kt % 3) * VT_E;
        const unsigned char* Msb = Ms0 + (kt % 3) * 64;

        // bias prefetch
        float2 bv0[8], bv1[8];
#pragma unroll
        for (int ni = 0; ni < 8; ni++) {
            bv0[ni] = *(const float2*)(bias0 + kk0 + ni * 8 + 2 * tig);
            bv1[ni] = *(const float2*)(bias1 + kk0 + ni * 8 + 2 * tig);
        }

        // warp-uniform "tile has any masked key" flag
        const uint4* mw = (const uint4*)Msb;
        uint4 w0 = mw[0], w1 = mw[1], w2 = mw[2], w3 = mw[3];
        bool tmask = ((w0.x | w0.y | w0.z | w0.w | w1.x | w1.y | w1.z | w1.w |
                       w2.x | w2.y | w2.z | w2.w | w3.x | w3.y | w3.z | w3.w) != 0u)
                     | qmask;

        // S = Q @ K^T
        float sf[8][4];
#pragma unroll
        for (int ni = 0; ni < 8; ni++)
#pragma unroll
            for (int q = 0; q < 4; q++) sf[ni][q] = 0.f;
#pragma unroll
        for (int p = 0; p < 2; p++) {
#pragma unroll
            for (int ni = 0; ni < 8; ni++) {
                uint32_t bq[4];
                ldsm_x4(bq, smem_u32(&Ksb[(ni * 8 + b_lr) * KS_H + p * 32 + b_lc]));
                mma16(sf[ni], qf[2 * p],     bq);
                mma16(sf[ni], qf[2 * p + 1], bq + 2);
            }
        }

        // bias + (rare) mask, row max
        float mloc0 = -FLT_MAX, mloc1 = -FLT_MAX;
        if (!tmask) {
#pragma unroll
            for (int ni = 0; ni < 8; ni++) {
                sf[ni][0] = fmaf(bv0[ni].x, LOG2E_, sf[ni][0]);
                sf[ni][1] = fmaf(bv0[ni].y, LOG2E_, sf[ni][1]);
                sf[ni][2] = fmaf(bv1[ni].x, LOG2E_, sf[ni][2]);
                sf[ni][3] = fmaf(bv1[ni].y, LOG2E_, sf[ni][3]);
                mloc0 = fmaxf(mloc0, fmaxf(sf[ni][0], sf[ni][1]));
                mloc1 = fmaxf(mloc1, fmaxf(sf[ni][2], sf[ni][3]));
            }
        } else {
#pragma unroll
            for (int ni = 0; ni < 8; ni++) {
                bool km0 = Msb[ni * 8 + 2 * tig] != 0;
                bool km1 = Msb[ni * 8 + 2 * tig + 1] != 0;
                sf[ni][0] = (qm0 | km0) ? -FLT_MAX : fmaf(bv0[ni].x, LOG2E_, sf[ni][0]);
                sf[ni][1] = (qm0 | km1) ? -FLT_MAX : fmaf(bv0[ni].y, LOG2E_, sf[ni][1]);
                sf[ni][2] = (qm1 | km0) ? -FLT_MAX : fmaf(bv1[ni].x, LOG2E_, sf[ni][2]);
                sf[ni][3] = (qm1 | km1) ? -FLT_MAX : fmaf(bv1[ni].y, LOG2E_, sf[ni][3]);
                mloc0 = fmaxf(mloc0, fmaxf(sf[ni][0], sf[ni][1]));
                mloc1 = fmaxf(mloc1, fmaxf(sf[ni][2], sf[ni][3]));
            }
        }
        mloc0 = fmaxf(mloc0, __shfl_xor_sync(0xffffffffu, mloc0, 1));
        mloc0 = fmaxf(mloc0, __shfl_xor_sync(0xffffffffu, mloc0, 2));
        mloc1 = fmaxf(mloc1, __shfl_xor_sync(0xffffffffu, mloc1, 1));
        mloc1 = fmaxf(mloc1, __shfl_xor_sync(0xffffffffu, mloc1, 2));

        float nm0 = fmaxf(m0, mloc0), nm1 = fmaxf(m1, mloc1);
        if ((nm0 != m0) | (nm1 != m1)) {
            float a0 = ex2(m0 - nm0), a1 = ex2(m1 - nm1);
            ol[0] *= a0; ol[1] *= a0; ol[2] *= a1; ol[3] *= a1;
#pragma unroll
            for (int df = 0; df < 8; df++) {
                of[df][0] *= a0; of[df][1] *= a0;
                of[df][2] *= a1; of[df][3] *= a1;
            }
            m0 = nm0; m1 = nm1;
        }

        // p = 2^(s - m), computed directly in fp16x2 on MUFU; feeds PV AND l
        uint32_t ph[8][2];
#pragma unroll
        for (int ni = 0; ni < 8; ni++) {
            ph[ni][0] = ex2_h2(sf[ni][0] - m0, sf[ni][1] - m0);
            ph[ni][1] = ex2_h2(sf[ni][2] - m1, sf[ni][3] - m1);
        }

        // O += P @ V, and l += P @ 1 (ones-mma: exact fp32 row sums)
#pragma unroll
        for (int p = 0; p < 2; p++) {
            uint32_t af0[4] = { ph[4*p    ][0], ph[4*p    ][1],
                                ph[4*p + 1][0], ph[4*p + 1][1] };
            uint32_t af1[4] = { ph[4*p + 2][0], ph[4*p + 2][1],
                                ph[4*p + 3][0], ph[4*p + 3][1] };
            mma16(ol, af0, ones);
            mma16(ol, af1, ones);
#pragma unroll
            for (int df = 0; df < 8; df++) {
                uint32_t bq[4];
                ldsm_x4(bq, smem_u32(&Vtb[(df * 8 + b_lr) * VT_H + p * 32 + b_lc]));
                mma16(of[df], af0, bq);
                mma16(of[df], af1, bq + 2);
            }
        }
    }

    float inv0 = 1.f / ol[0], inv1 = 1.f / ol[2];
    __half* op0 = g_att + ((size_t)(b * N_ + qrow))     * HD_ + h * D_;
    __half* op1 = g_att + ((size_t)(b * N_ + qrow + 8)) * HD_ + h * D_;
#pragma unroll
    for (int df = 0; df < 8; df++) {
        *(__half2*)(op0 + df * 8 + 2 * tig) =
            __floats2half2_rn(of[df][0] * inv0, of[df][1] * inv0);
        *(__half2*)(op1 + df * 8 + 2 * tig) =
            __floats2half2_rn(of[df][2] * inv1, of[df][3] * inv1);
    }
}

// ---------------------------------------------------------------------------
extern "C" void kernel_launch(void* const* d_in, const int* in_sizes, int n_in,
                              void* d_out, int out_size) {
    const float*         x        = (const float*)d_in[0];
    const float*         pos_bias = (const float*)d_in[1];
    const float*         Wqkv     = (const float*)d_in[2];
    const float*         Wout     = (const float*)d_in[3];
    const unsigned char* mask     = (const unsigned char*)d_in[4];
    float*               out      = (float*)d_out;

    __half *xh, *wqkvt, *woutt, *att, *qkvh;
    cudaGetSymbolAddress((void**)&xh,    g_xh);
    cudaGetSymbolAddress((void**)&wqkvt, g_wqkvt);
    cudaGetSymbolAddress((void**)&woutt, g_woutt);
    cudaGetSymbolAddress((void**)&att,   g_att);
    cudaGetSymbolAddress((void**)&qkvh,  g_qkvh);

    conv_half<<<1024, 256>>>(x, xh, (M_ * C_) / 4);
    transpose_half<<<dim3(QKVC_/32, C_/32), dim3(32, 8)>>>(Wqkv, wqkvt, C_, QKVC_);
    transpose_half<<<dim3(HD_/32,  HD_/32), dim3(32, 8)>>>(Wout, woutt, HD_, HD_);

    cudaFuncSetAttribute(gemm_h<QKVC_, true>,
                         cudaFuncAttributeMaxDynamicSharedMemorySize, GEMM_SMEM);
    gemm_h<QKVC_, true><<<dim3(QKVC_/128, M_/128), 256, GEMM_SMEM>>>(xh, wqkvt, qkvh);

    scatter_qkv<<<dim3(H_, M_/64), 256>>>();

    cudaFuncSetAttribute(attn_h,
                         cudaFuncAttributeMaxDynamicSharedMemorySize, ATTN_SMEM_BYTES);
    attn_h<<<dim3(B_, N_/128, H_), 256, ATTN_SMEM_BYTES>>>(pos_bias, mask);

    cudaFuncSetAttribute(gemm_h<HD_, false>,
                         cudaFuncAttributeMaxDynamicSharedMemorySize, GEMM_SMEM);
    gemm_h<HD_, false><<<dim3(HD_/128, M_/128), 256, GEMM_SMEM>>>(att, woutt, out);
}